// round 3
// baseline (speedup 1.0000x reference)
#include <cuda_runtime.h>
#include <math.h>

// Problem constants
#define L_SEQ 1024
#define B_SZ  16
#define D_SZ  1024
#define M_TOT (L_SEQ * B_SZ)     // 16384 rows of X
#define K_TOT D_SZ               // 1024
#define N_TOT (3 * D_SZ)         // 3072 cols of W
#define PLANE (M_TOT * D_SZ)     // 16,777,216 elements per plane

// Scratch: 3 planes (u0, sigmoid(u1+b1), sigmoid(u2+b2)), each [M_TOT, D] fp32.
// __device__ global => allowed (no runtime allocation).
__device__ float g_u[3ull * PLANE];

// ---------------------------------------------------------------------------
// GEMM: U = X @ W with fused bias + sigmoid epilogue, scattered into planes.
// Classic SIMT SGEMM: BM=128, BN=128, BK=16, 256 threads, 8x8 per thread.
// ---------------------------------------------------------------------------
#define BM 128
#define BN 128
#define BK 16
#define TM 8
#define TN 8

__device__ __forceinline__ float sigmoidf_(float v) {
    return 1.0f / (1.0f + expf(-v));
}

__global__ __launch_bounds__(256, 2)
void sru_gemm_kernel(const float* __restrict__ X,
                     const float* __restrict__ W,
                     const float* __restrict__ bias)
{
    __shared__ float As[BK][BM];   // A stored transposed
    __shared__ float Bs[BK][BN];

    const int bn = blockIdx.x;     // along N (24 blocks)
    const int bm = blockIdx.y;     // along M (128 blocks)
    const int tid = threadIdx.x;   // 0..255
    const int tx = tid % 16;       // N direction
    const int ty = tid / 16;       // M direction

    // A tile load mapping: 128 rows x 16 cols = 512 float4; 2 per thread
    const int arow = tid >> 2;        // 0..63 (+64 second iter)
    const int acol4 = (tid & 3) * 4;  // 0,4,8,12
    // B tile load mapping: 16 rows x 128 cols = 512 float4; 2 per thread
    const int brow = tid >> 5;        // 0..7 (+8 second iter)
    const int bcol4 = (tid & 31) * 4; // 0..124

    const float* Xb = X + (size_t)bm * BM * K_TOT;
    const float* Wb = W + (size_t)bn * BN;

    float acc[TM][TN];
    #pragma unroll
    for (int i = 0; i < TM; i++)
        #pragma unroll
        for (int j = 0; j < TN; j++) acc[i][j] = 0.0f;

    for (int k0 = 0; k0 < K_TOT; k0 += BK) {
        // Load A tile (transpose into As[k][m])
        #pragma unroll
        for (int r = 0; r < 2; r++) {
            int row = arow + r * 64;
            float4 a = *reinterpret_cast<const float4*>(Xb + (size_t)row * K_TOT + k0 + acol4);
            As[acol4 + 0][row] = a.x;
            As[acol4 + 1][row] = a.y;
            As[acol4 + 2][row] = a.z;
            As[acol4 + 3][row] = a.w;
        }
        // Load B tile
        #pragma unroll
        for (int r = 0; r < 2; r++) {
            int row = brow + r * 8;
            float4 b = *reinterpret_cast<const float4*>(Wb + (size_t)(k0 + row) * N_TOT + bcol4);
            *reinterpret_cast<float4*>(&Bs[row][bcol4]) = b;
        }
        __syncthreads();

        #pragma unroll
        for (int k = 0; k < BK; k++) {
            float a[TM], b[TN];
            #pragma unroll
            for (int i = 0; i < TM; i++) a[i] = As[k][ty * TM + i];
            #pragma unroll
            for (int j = 0; j < TN; j++) b[j] = Bs[k][tx * TN + j];
            #pragma unroll
            for (int i = 0; i < TM; i++)
                #pragma unroll
                for (int j = 0; j < TN; j++)
                    acc[i][j] = fmaf(a[i], b[j], acc[i][j]);
        }
        __syncthreads();
    }

    // Epilogue: n -> (d = n/3, gate j = n%3); fuse bias + sigmoid for gates.
    const int m0 = bm * BM + ty * TM;
    const int n0 = bn * BN + tx * TN;
    #pragma unroll
    for (int i = 0; i < TM; i++) {
        const int m = m0 + i;
        #pragma unroll
        for (int j = 0; j < TN; j++) {
            const int n = n0 + j;
            const int gate = n % 3;
            const int d = n / 3;
            float v = acc[i][j];
            size_t off = (size_t)m * D_SZ + d;
            if (gate == 0) {
                g_u[off] = v;
            } else if (gate == 1) {
                g_u[PLANE + off] = sigmoidf_(v + bias[d]);
            } else {
                g_u[2ull * PLANE + off] = sigmoidf_(v + bias[D_SZ + d]);
            }
        }
    }
}

// ---------------------------------------------------------------------------
// Scan: one thread per (b,d) lane; 1024 sequential steps.
// Plane offset for step t is t*(B*D) + idx  (coalesced across the warp).
// ---------------------------------------------------------------------------
__global__ __launch_bounds__(128)
void sru_scan_kernel(const float* __restrict__ x,
                     const float* __restrict__ c0,
                     float* __restrict__ out)
{
    const int idx = blockIdx.x * blockDim.x + threadIdx.x;   // 0..B*D-1
    if (idx >= B_SZ * D_SZ) return;

    float c = c0[idx];

    const float* __restrict__ u0 = g_u;
    const float* __restrict__ g1 = g_u + PLANE;
    const float* __restrict__ g2 = g_u + 2ull * PLANE;

    #pragma unroll 8
    for (int t = 0; t < L_SEQ; t++) {
        const size_t o = (size_t)t * (B_SZ * D_SZ) + idx;
        const float u0v = u0[o];
        const float g1v = g1[o];
        const float g2v = g2[o];
        const float xv  = x[o];
        c = (c - u0v) * g1v + u0v;
        const float h = (tanhf(c) - xv) * g2v + xv;
        out[o] = h;
    }
    out[(size_t)PLANE + idx] = c;   // c_last
}

// ---------------------------------------------------------------------------
// Launch
// ---------------------------------------------------------------------------
extern "C" void kernel_launch(void* const* d_in, const int* in_sizes, int n_in,
                              void* d_out, int out_size)
{
    const float* x      = (const float*)d_in[0];  // (L,B,D)
    const float* weight = (const float*)d_in[1];  // (D, 3D)
    const float* bias   = (const float*)d_in[2];  // (2D)
    const float* c0     = (const float*)d_in[3];  // (B,D)
    float* out = (float*)d_out;                   // h (L*B*D) then c_last (B*D)

    dim3 gemm_grid(N_TOT / BN, M_TOT / BM);       // (24, 128)
    sru_gemm_kernel<<<gemm_grid, 256>>>(x, weight, bias);

    sru_scan_kernel<<<128, 128>>>(x, c0, out);
}

// round 5
// speedup vs baseline: 2.8608x; 2.8608x over previous
#include <cuda_runtime.h>
#include <cuda_bf16.h>
#include <cstdint>
#include <math.h>

// ---------------------------------------------------------------------------
// Problem constants
// ---------------------------------------------------------------------------
#define L_SEQ 1024
#define B_SZ  16
#define D_SZ  1024
#define M_X   (L_SEQ * B_SZ)        // 16384 x-rows
#define N_W   3072                  // weight rows (gate-major permuted)
#define NCHUNK 48                   // logical k-chunks of 64 (3 split terms x 16)
#define PLANE ((size_t)M_X * D_SZ)  // 16,777,216

#define NSEG 16
#define SEG_T (L_SEQ / NSEG)        // 64

// ---------------------------------------------------------------------------
// Scratch (__device__ globals: allocation-free)
// ---------------------------------------------------------------------------
// Packed, pre-swizzled bf16 operands: [chunk][row][128B swizzled]; hi chunks
// 0..15, lo chunks 16..31.
__device__ __align__(1024) __nv_bfloat16 g_xc[(size_t)M_X * 2048];   // 64 MiB
__device__ __align__(1024) __nv_bfloat16 g_wc[(size_t)N_W * 2048];   // 12 MiB
// GEMM output planes: u0, sigmoid(u1+b1), sigmoid(u2+b2), each [M_X, D]
__device__ float g_u[3ull * PLANE];                                   // 201 MB
// Segmented-scan scratch
__device__ float g_segAx[NSEG * B_SZ * D_SZ];
__device__ float g_segBx[NSEG * B_SZ * D_SZ];
__device__ float g_cst  [NSEG * B_SZ * D_SZ];

// ---------------------------------------------------------------------------
// helpers
// ---------------------------------------------------------------------------
__device__ __forceinline__ uint32_t smem_u32(const void* p) {
    return (uint32_t)__cvta_generic_to_shared(p);
}
__device__ __forceinline__ void cp_async16(uint32_t dst, const void* src) {
    asm volatile("cp.async.cg.shared.global [%0], [%1], 16;" :: "r"(dst), "l"(src));
}
__device__ __forceinline__ void cp_commit() {
    asm volatile("cp.async.commit_group;");
}
template <int N>
__device__ __forceinline__ void cp_wait() {
    asm volatile("cp.async.wait_group %0;" :: "n"(N));
}
__device__ __forceinline__ void ldsm_x4(uint32_t& r0, uint32_t& r1, uint32_t& r2,
                                        uint32_t& r3, uint32_t addr) {
    asm volatile("ldmatrix.sync.aligned.m8n8.x4.shared.b16 {%0,%1,%2,%3}, [%4];"
                 : "=r"(r0), "=r"(r1), "=r"(r2), "=r"(r3) : "r"(addr));
}
__device__ __forceinline__ void mma_bf16(float* d, const uint32_t* a, const uint32_t* b) {
    asm volatile(
        "mma.sync.aligned.m16n8k16.row.col.f32.bf16.bf16.f32 "
        "{%0,%1,%2,%3}, {%4,%5,%6,%7}, {%8,%9}, {%0,%1,%2,%3};"
        : "+f"(d[0]), "+f"(d[1]), "+f"(d[2]), "+f"(d[3])
        : "r"(a[0]), "r"(a[1]), "r"(a[2]), "r"(a[3]), "r"(b[0]), "r"(b[1]));
}
__device__ __forceinline__ uint32_t pack_bf16(float a, float b) {
    __nv_bfloat16 ha = __float2bfloat16(a);
    __nv_bfloat16 hb = __float2bfloat16(b);
    return (uint32_t)__bfloat16_as_ushort(ha) | ((uint32_t)__bfloat16_as_ushort(hb) << 16);
}
__device__ __forceinline__ void split_hl(float x, float& hi, float& lo) {
    __nv_bfloat16 h = __float2bfloat16(x);
    hi = __bfloat162float(h);
    lo = x - hi;
}

// ---------------------------------------------------------------------------
// conv_x: X[m][k] fp32 -> packed swizzled bf16 tiles
// byte addr = ((chunk*M_X + m)*128) + (2*(k%64) XOR ((m&7)<<4))
// ---------------------------------------------------------------------------
__global__ __launch_bounds__(256)
void conv_x_kernel(const float* __restrict__ X) {
    int gid = blockIdx.x * blockDim.x + threadIdx.x;   // M_X * 128 threads
    int m  = gid >> 7;
    int k  = (gid & 127) * 8;

    const float4* xp = reinterpret_cast<const float4*>(X + (size_t)m * 1024 + k);
    float4 x0 = xp[0];
    float4 x1 = xp[1];
    float h[8], l[8];
    split_hl(x0.x, h[0], l[0]); split_hl(x0.y, h[1], l[1]);
    split_hl(x0.z, h[2], l[2]); split_hl(x0.w, h[3], l[3]);
    split_hl(x1.x, h[4], l[4]); split_hl(x1.y, h[5], l[5]);
    split_hl(x1.z, h[6], l[6]); split_hl(x1.w, h[7], l[7]);

    uint4 hv, lv;
    hv.x = pack_bf16(h[0], h[1]); hv.y = pack_bf16(h[2], h[3]);
    hv.z = pack_bf16(h[4], h[5]); hv.w = pack_bf16(h[6], h[7]);
    lv.x = pack_bf16(l[0], l[1]); lv.y = pack_bf16(l[2], l[3]);
    lv.z = pack_bf16(l[4], l[5]); lv.w = pack_bf16(l[6], l[7]);

    int chunk = k >> 6;
    uint32_t b = (uint32_t)(k & 63) * 2;
    uint32_t sw = b ^ (((uint32_t)m & 7u) << 4);
    char* base = (char*)g_xc;
    *reinterpret_cast<uint4*>(base + ((size_t)chunk * M_X + m) * 128 + sw) = hv;
    *reinterpret_cast<uint4*>(base + ((size_t)(chunk + 16) * M_X + m) * 128 + sw) = lv;
}

// ---------------------------------------------------------------------------
// conv_w: W[k][3d+gate] fp32 -> packed swizzled bf16, rows n' = gate*1024+d
// ---------------------------------------------------------------------------
__global__ __launch_bounds__(256)
void conv_w_kernel(const float* __restrict__ W) {
    int gid = blockIdx.x * blockDim.x + threadIdx.x;   // N_W * 512 threads
    int np = gid % N_W;
    int k  = (gid / N_W) * 2;

    int gate = np >> 10;
    int d    = np & 1023;
    int col  = 3 * d + gate;

    float w0 = W[(size_t)k * N_W + col];
    float w1 = W[(size_t)(k + 1) * N_W + col];
    float h0, l0, h1, l1;
    split_hl(w0, h0, l0);
    split_hl(w1, h1, l1);

    int chunk = k >> 6;
    uint32_t b = (uint32_t)(k & 63) * 2;
    uint32_t sw = b ^ (((uint32_t)np & 7u) << 4);
    char* base = (char*)g_wc;
    *reinterpret_cast<uint32_t*>(base + ((size_t)chunk * N_W + np) * 128 + sw) = pack_bf16(h0, h1);
    *reinterpret_cast<uint32_t*>(base + ((size_t)(chunk + 16) * N_W + np) * 128 + sw) = pack_bf16(l0, l1);
}

// ---------------------------------------------------------------------------
// mma.sync GEMM: C[np][m] = sum_k Wc[np][k] * Xc[m][k]  (3-term bf16 split)
// CTA tile 256(np) x 128(m) x 64(k); 512 threads = 16 warps (4 np x 4 m);
// warp tile 64(np) x 32(m). 4-stage cp.async pipeline over 48 chunks.
// ---------------------------------------------------------------------------
#define STAGES 4
#define A_BYTES 32768            // 256 rows x 128B
#define B_BYTES 16384            // 128 rows x 128B
#define STAGE_BYTES (A_BYTES + B_BYTES)
#define SMEM_TOTAL (STAGES * STAGE_BYTES)   // 196608
#define EPI_PITCH 264            // floats per staging row (256 + pad)

__global__ __launch_bounds__(512, 1)
void sru_gemm_mma(const float* __restrict__ bias) {
    extern __shared__ char smem[];
    const uint32_t sbase = smem_u32(smem);
    const int tid = threadIdx.x;
    const int wid = tid >> 5;
    const int l = tid & 31;

    const int bn = blockIdx.x;    // m tiles (128)
    const int bm = blockIdx.y;    // np tiles (12)

    const int npwarp = (wid & 3) * 64;
    const int mwarp  = (wid >> 2) * 32;

    // ldmatrix per-lane addressing constants
    const uint32_t swz = (uint32_t)(l & 7) << 4;
    const uint32_t aRow = npwarp + (l & 15);
    const uint32_t aHalf = (uint32_t)(l >> 4) << 4;     // 0 or 16
    const uint32_t bRow = mwarp + (l & 7) + ((l & 16) >> 1);
    const uint32_t bHalf = (uint32_t)(l & 8) << 1;      // 0 or 16

    // cp.async sources for this CTA
    const char* aSrcBase = (const char*)g_wc + (size_t)bm * 256 * 128;
    const char* bSrcBase = (const char*)g_xc + (size_t)bn * 128 * 128;

    float cacc[4][4][4];
    #pragma unroll
    for (int i = 0; i < 4; i++)
        #pragma unroll
        for (int j = 0; j < 4; j++)
            #pragma unroll
            for (int r = 0; r < 4; r++) cacc[i][j][r] = 0.0f;

    auto issue_chunk = [&](int i, int slot) {
        int wc_ = (i < 16) ? i : (i - 16);
        int xc_ = (i < 32) ? i : (i - 32);
        const char* as = aSrcBase + (size_t)wc_ * N_W * 128;
        const char* bs = bSrcBase + (size_t)xc_ * M_X * 128;
        uint32_t ad = sbase + slot * STAGE_BYTES;
        uint32_t bd = ad + A_BYTES;
        #pragma unroll
        for (int r = 0; r < 4; r++) {
            int off = (tid + r * 512) * 16;
            cp_async16(ad + off, as + off);
        }
        #pragma unroll
        for (int r = 0; r < 2; r++) {
            int off = (tid + r * 512) * 16;
            cp_async16(bd + off, bs + off);
        }
        cp_commit();
    };

    // prologue: stages-1 chunks in flight
    issue_chunk(0, 0);
    issue_chunk(1, 1);
    issue_chunk(2, 2);

    for (int j = 0; j < NCHUNK; j++) {
        const int slot = j & 3;
        cp_wait<2>();
        __syncthreads();
        if (j + 3 < NCHUNK) issue_chunk(j + 3, (j + 3) & 3);

        const uint32_t aBase = sbase + slot * STAGE_BYTES;
        const uint32_t bBase = aBase + A_BYTES;

        #pragma unroll
        for (int ks = 0; ks < 4; ks++) {
            const uint32_t kb = ks * 32;
            uint32_t a[4][4], b[2][4];
            #pragma unroll
            for (int t = 0; t < 4; t++) {
                uint32_t addr = aBase + (aRow + t * 16) * 128 + ((kb + aHalf) ^ swz);
                ldsm_x4(a[t][0], a[t][1], a[t][2], a[t][3], addr);
            }
            #pragma unroll
            for (int g = 0; g < 2; g++) {
                uint32_t addr = bBase + (bRow + g * 16) * 128 + ((kb + bHalf) ^ swz);
                ldsm_x4(b[g][0], b[g][1], b[g][2], b[g][3], addr);
            }
            #pragma unroll
            for (int i = 0; i < 4; i++)
                #pragma unroll
                for (int jj = 0; jj < 4; jj++)
                    mma_bf16(cacc[i][jj], a[i], &b[jj >> 1][(jj & 1) * 2]);
        }
    }

    // ---------------- epilogue ----------------
    __syncthreads();   // done reading pipeline smem
    float* stag = (float*)smem;    // [128 m][EPI_PITCH np]

    #pragma unroll
    for (int i = 0; i < 4; i++) {
        const int np0 = npwarp + i * 16 + (l >> 2);
        #pragma unroll
        for (int jj = 0; jj < 4; jj++) {
            const int m0 = mwarp + jj * 8 + (l & 3) * 2;
            stag[(size_t)m0 * EPI_PITCH + np0]           = cacc[i][jj][0];
            stag[(size_t)(m0 + 1) * EPI_PITCH + np0]     = cacc[i][jj][1];
            stag[(size_t)m0 * EPI_PITCH + np0 + 8]       = cacc[i][jj][2];
            stag[(size_t)(m0 + 1) * EPI_PITCH + np0 + 8] = cacc[i][jj][3];
        }
    }
    __syncthreads();

    // This CTA covers a single gate: np range [bm*256, bm*256+256)
    const int gate = bm >> 2;
    const int d0 = (bm & 3) * 256;
    float* plane = g_u + (size_t)gate * PLANE;

    for (int idx = tid; idx < 128 * 256; idx += 512) {
        const int m = idx >> 8;
        const int np = idx & 255;
        float v = stag[(size_t)m * EPI_PITCH + np];
        if (gate) {
            const float bv = bias[(gate - 1) * D_SZ + d0 + np];
            v = 1.0f / (1.0f + __expf(-(v + bv)));
        }
        plane[(size_t)(bn * 128 + m) * D_SZ + d0 + np] = v;
    }
}

// ---------------------------------------------------------------------------
// Segmented scan.  c_t = g1*c + u0*(1-g1)  (affine in c)
// ---------------------------------------------------------------------------
__global__ __launch_bounds__(256)
void scan_seg_kernel() {
    const int gid = blockIdx.x * blockDim.x + threadIdx.x;  // NSEG * 16384
    const int lanei = gid & 16383;
    const int s = gid >> 14;
    const float* __restrict__ u0 = g_u;
    const float* __restrict__ g1 = g_u + PLANE;
    size_t o = (size_t)s * SEG_T * 16384 + lanei;
    float A = 1.0f, Bc = 0.0f;
    #pragma unroll 8
    for (int t = 0; t < SEG_T; t++) {
        const float a = g1[o];
        const float u = u0[o];
        Bc = Bc * a + u * (1.0f - a);
        A *= a;
        o += 16384;
    }
    g_segAx[gid] = A;
    g_segBx[gid] = Bc;
}

__global__ __launch_bounds__(256)
void scan_prefix_kernel(const float* __restrict__ c0) {
    const int lanei = blockIdx.x * blockDim.x + threadIdx.x;  // 16384
    float c = c0[lanei];
    #pragma unroll
    for (int s = 0; s < NSEG; s++) {
        g_cst[s * 16384 + lanei] = c;
        c = g_segAx[s * 16384 + lanei] * c + g_segBx[s * 16384 + lanei];
    }
}

__global__ __launch_bounds__(256)
void scan_out_kernel(const float* __restrict__ x, float* __restrict__ out) {
    const int gid = blockIdx.x * blockDim.x + threadIdx.x;  // NSEG * 16384
    const int lanei = gid & 16383;
    const int s = gid >> 14;
    const float* __restrict__ u0 = g_u;
    const float* __restrict__ g1 = g_u + PLANE;
    const float* __restrict__ g2 = g_u + 2ull * PLANE;
    float c = g_cst[s * 16384 + lanei];
    size_t o = (size_t)s * SEG_T * 16384 + lanei;
    #pragma unroll 4
    for (int t = 0; t < SEG_T; t++) {
        const float u = u0[o];
        const float a = g1[o];
        const float b = g2[o];
        const float xv = x[o];
        c = (c - u) * a + u;
        out[o] = (tanhf(c) - xv) * b + xv;
        o += 16384;
    }
    if (s == NSEG - 1) out[PLANE + lanei] = c;  // c_last
}

// ---------------------------------------------------------------------------
// Launch
// ---------------------------------------------------------------------------
extern "C" void kernel_launch(void* const* d_in, const int* in_sizes, int n_in,
                              void* d_out, int out_size) {
    const float* x      = (const float*)d_in[0];  // (L,B,D)
    const float* weight = (const float*)d_in[1];  // (D, 3D)
    const float* bias   = (const float*)d_in[2];  // (2D)
    const float* c0     = (const float*)d_in[3];  // (B,D)
    float* out = (float*)d_out;                   // h then c_last

    conv_x_kernel<<<(M_X * 128) / 256, 256>>>(x);
    conv_w_kernel<<<(N_W * 512) / 256, 256>>>(weight);

    static int smem_set = 0;
    if (!smem_set) {
        cudaFuncSetAttribute(sru_gemm_mma, cudaFuncAttributeMaxDynamicSharedMemorySize,
                             SMEM_TOTAL);
        smem_set = 1;
    }
    sru_gemm_mma<<<dim3(M_X / 128, N_W / 256), 512, SMEM_TOTAL>>>(bias);

    scan_seg_kernel<<<(NSEG * 16384) / 256, 256>>>();
    scan_prefix_kernel<<<16384 / 256, 256>>>(c0);
    scan_out_kernel<<<(NSEG * 16384) / 256, 256>>>(x, out);
}

// round 6
// speedup vs baseline: 3.1103x; 1.0872x over previous
#include <cuda_runtime.h>
#include <cuda_bf16.h>
#include <cstdint>
#include <math.h>

// ---------------------------------------------------------------------------
// Problem constants
// ---------------------------------------------------------------------------
#define L_SEQ 1024
#define B_SZ  16
#define D_SZ  1024
#define M_X   (L_SEQ * B_SZ)        // 16384 x-rows
#define N_W   3072                  // weight rows (gate-major permuted)
#define NPOS  16                    // physical k-positions (chunks of 64)
#define PLANE ((size_t)M_X * D_SZ)  // 16,777,216

#define NSEG 16
#define SEG_T (L_SEQ / NSEG)        // 64

// ---------------------------------------------------------------------------
// Scratch (__device__ globals: allocation-free)
// ---------------------------------------------------------------------------
// Packed, pre-swizzled bf16 operands: [chunk][row][128B swizzled]; hi chunks
// 0..15, lo chunks 16..31.
__device__ __align__(1024) __nv_bfloat16 g_xc[(size_t)M_X * 2048];   // 64 MiB
__device__ __align__(1024) __nv_bfloat16 g_wc[(size_t)N_W * 2048];   // 12 MiB
// GEMM output planes: u0, sigmoid(u1+b1), sigmoid(u2+b2), each [M_X, D]
__device__ float g_u[3ull * PLANE];                                   // 201 MB
// Segmented-scan scratch
__device__ float g_segAx[NSEG * B_SZ * D_SZ];
__device__ float g_segBx[NSEG * B_SZ * D_SZ];
__device__ float g_cst  [NSEG * B_SZ * D_SZ];

// ---------------------------------------------------------------------------
// helpers
// ---------------------------------------------------------------------------
__device__ __forceinline__ uint32_t smem_u32(const void* p) {
    return (uint32_t)__cvta_generic_to_shared(p);
}
__device__ __forceinline__ void cp_async16(uint32_t dst, const void* src) {
    asm volatile("cp.async.cg.shared.global [%0], [%1], 16;" :: "r"(dst), "l"(src));
}
__device__ __forceinline__ void cp_commit() {
    asm volatile("cp.async.commit_group;");
}
template <int N>
__device__ __forceinline__ void cp_wait() {
    asm volatile("cp.async.wait_group %0;" :: "n"(N));
}
__device__ __forceinline__ void ldsm_x4(uint32_t& r0, uint32_t& r1, uint32_t& r2,
                                        uint32_t& r3, uint32_t addr) {
    asm volatile("ldmatrix.sync.aligned.m8n8.x4.shared.b16 {%0,%1,%2,%3}, [%4];"
                 : "=r"(r0), "=r"(r1), "=r"(r2), "=r"(r3) : "r"(addr));
}
__device__ __forceinline__ void mma_bf16(float* d, const uint32_t* a, const uint32_t* b) {
    asm volatile(
        "mma.sync.aligned.m16n8k16.row.col.f32.bf16.bf16.f32 "
        "{%0,%1,%2,%3}, {%4,%5,%6,%7}, {%8,%9}, {%0,%1,%2,%3};"
        : "+f"(d[0]), "+f"(d[1]), "+f"(d[2]), "+f"(d[3])
        : "r"(a[0]), "r"(a[1]), "r"(a[2]), "r"(a[3]), "r"(b[0]), "r"(b[1]));
}
__device__ __forceinline__ uint32_t pack_bf16(float a, float b) {
    __nv_bfloat16 ha = __float2bfloat16(a);
    __nv_bfloat16 hb = __float2bfloat16(b);
    return (uint32_t)__bfloat16_as_ushort(ha) | ((uint32_t)__bfloat16_as_ushort(hb) << 16);
}
__device__ __forceinline__ void split_hl(float x, float& hi, float& lo) {
    __nv_bfloat16 h = __float2bfloat16(x);
    hi = __bfloat162float(h);
    lo = x - hi;
}

// ---------------------------------------------------------------------------
// conv_x: X[m][k] fp32 -> packed swizzled bf16 tiles
// byte addr = ((chunk*M_X + m)*128) + (2*(k%64) XOR ((m&7)<<4))
// ---------------------------------------------------------------------------
__global__ __launch_bounds__(256)
void conv_x_kernel(const float* __restrict__ X) {
    int gid = blockIdx.x * blockDim.x + threadIdx.x;   // M_X * 128 threads
    int m  = gid >> 7;
    int k  = (gid & 127) * 8;

    const float4* xp = reinterpret_cast<const float4*>(X + (size_t)m * 1024 + k);
    float4 x0 = xp[0];
    float4 x1 = xp[1];
    float h[8], l[8];
    split_hl(x0.x, h[0], l[0]); split_hl(x0.y, h[1], l[1]);
    split_hl(x0.z, h[2], l[2]); split_hl(x0.w, h[3], l[3]);
    split_hl(x1.x, h[4], l[4]); split_hl(x1.y, h[5], l[5]);
    split_hl(x1.z, h[6], l[6]); split_hl(x1.w, h[7], l[7]);

    uint4 hv, lv;
    hv.x = pack_bf16(h[0], h[1]); hv.y = pack_bf16(h[2], h[3]);
    hv.z = pack_bf16(h[4], h[5]); hv.w = pack_bf16(h[6], h[7]);
    lv.x = pack_bf16(l[0], l[1]); lv.y = pack_bf16(l[2], l[3]);
    lv.z = pack_bf16(l[4], l[5]); lv.w = pack_bf16(l[6], l[7]);

    int chunk = k >> 6;
    uint32_t b = (uint32_t)(k & 63) * 2;
    uint32_t sw = b ^ (((uint32_t)m & 7u) << 4);
    char* base = (char*)g_xc;
    *reinterpret_cast<uint4*>(base + ((size_t)chunk * M_X + m) * 128 + sw) = hv;
    *reinterpret_cast<uint4*>(base + ((size_t)(chunk + 16) * M_X + m) * 128 + sw) = lv;
}

// ---------------------------------------------------------------------------
// conv_w: W[k][3d+gate] fp32 -> packed swizzled bf16, rows n' = gate*1024+d
// ---------------------------------------------------------------------------
__global__ __launch_bounds__(256)
void conv_w_kernel(const float* __restrict__ W) {
    int gid = blockIdx.x * blockDim.x + threadIdx.x;   // N_W * 512 threads
    int np = gid % N_W;
    int k  = (gid / N_W) * 2;

    int gate = np >> 10;
    int d    = np & 1023;
    int col  = 3 * d + gate;

    float w0 = W[(size_t)k * N_W + col];
    float w1 = W[(size_t)(k + 1) * N_W + col];
    float h0, l0, h1, l1;
    split_hl(w0, h0, l0);
    split_hl(w1, h1, l1);

    int chunk = k >> 6;
    uint32_t b = (uint32_t)(k & 63) * 2;
    uint32_t sw = b ^ (((uint32_t)np & 7u) << 4);
    char* base = (char*)g_wc;
    *reinterpret_cast<uint32_t*>(base + ((size_t)chunk * N_W + np) * 128 + sw) = pack_bf16(h0, h1);
    *reinterpret_cast<uint32_t*>(base + ((size_t)(chunk + 16) * N_W + np) * 128 + sw) = pack_bf16(l0, l1);
}

// ---------------------------------------------------------------------------
// mma.sync GEMM: C[np][m] = sum_k Wc[np][k] * Xc[m][k]  (3-term bf16 split)
// CTA tile 256(np) x 128(m) x 64(k); 512 threads = 16 warps (4 np x 4 m).
// Physical k-position loop: per position load Wh/Wl/Xh/Xl ONCE, run the
// three split passes (WhXh + WhXl + WlXh) into one accumulator.
// 2-stage x 96KB cp.async double buffer.
// ---------------------------------------------------------------------------
#define WH_OFF 0
#define WL_OFF 32768
#define XH_OFF 65536
#define XL_OFF 81920
#define STAGE_BYTES 98304        // 96 KB
#define STAGES 2
#define SMEM_TOTAL (STAGES * STAGE_BYTES)   // 196608
#define EPI_PITCH 264            // floats per staging row (256 + pad)

__global__ __launch_bounds__(512, 1)
void sru_gemm_mma(const float* __restrict__ bias) {
    extern __shared__ char smem[];
    const uint32_t sbase = smem_u32(smem);
    const int tid = threadIdx.x;
    const int wid = tid >> 5;
    const int l = tid & 31;

    const int bn = blockIdx.x;    // m tiles (128)
    const int bm = blockIdx.y;    // np tiles (12)

    const int npwarp = (wid & 3) * 64;
    const int mwarp  = (wid >> 2) * 32;

    // ldmatrix per-lane addressing constants
    const uint32_t swz = (uint32_t)(l & 7) << 4;
    const uint32_t aRow = npwarp + (l & 15);
    const uint32_t aHalf = (uint32_t)(l >> 4) << 4;     // 0 or 16
    const uint32_t bRow = mwarp + (l & 7) + ((l & 16) >> 1);
    const uint32_t bHalf = (uint32_t)(l & 8) << 1;      // 0 or 16

    // cp.async sources for this CTA
    const char* aSrcBase = (const char*)g_wc + (size_t)bm * 256 * 128;
    const char* bSrcBase = (const char*)g_xc + (size_t)bn * 128 * 128;

    float cacc[4][4][4];
    #pragma unroll
    for (int i = 0; i < 4; i++)
        #pragma unroll
        for (int j = 0; j < 4; j++)
            #pragma unroll
            for (int r = 0; r < 4; r++) cacc[i][j][r] = 0.0f;

    // Load one physical k-position: Wh, Wl (32KB each), Xh, Xl (16KB each)
    auto issue_pos = [&](int kc, int slot) {
        const uint32_t sb = sbase + slot * STAGE_BYTES;
        const char* wh = aSrcBase + (size_t)kc * N_W * 128;
        const char* wl = aSrcBase + (size_t)(kc + 16) * N_W * 128;
        const char* xh = bSrcBase + (size_t)kc * M_X * 128;
        const char* xl = bSrcBase + (size_t)(kc + 16) * M_X * 128;
        #pragma unroll
        for (int r = 0; r < 4; r++) {
            int off = (tid + r * 512) * 16;
            cp_async16(sb + WH_OFF + off, wh + off);
        }
        #pragma unroll
        for (int r = 0; r < 4; r++) {
            int off = (tid + r * 512) * 16;
            cp_async16(sb + WL_OFF + off, wl + off);
        }
        #pragma unroll
        for (int r = 0; r < 2; r++) {
            int off = (tid + r * 512) * 16;
            cp_async16(sb + XH_OFF + off, xh + off);
        }
        #pragma unroll
        for (int r = 0; r < 2; r++) {
            int off = (tid + r * 512) * 16;
            cp_async16(sb + XL_OFF + off, xl + off);
        }
        cp_commit();
    };

    issue_pos(0, 0);
    issue_pos(1, 1);

    for (int j = 0; j < NPOS; j++) {
        const int slot = j & 1;
        cp_wait<1>();
        __syncthreads();

        const uint32_t sb = sbase + slot * STAGE_BYTES;

        #pragma unroll
        for (int ks = 0; ks < 4; ks++) {
            const uint32_t kb = ks * 32;
            const uint32_t aCol = (kb + aHalf) ^ swz;
            const uint32_t bCol = (kb + bHalf) ^ swz;

            uint32_t bh[2][4], bl[2][4];
            #pragma unroll
            for (int g = 0; g < 2; g++) {
                ldsm_x4(bh[g][0], bh[g][1], bh[g][2], bh[g][3],
                        sb + XH_OFF + (bRow + g * 16) * 128 + bCol);
                ldsm_x4(bl[g][0], bl[g][1], bl[g][2], bl[g][3],
                        sb + XL_OFF + (bRow + g * 16) * 128 + bCol);
            }
            // pass 1+2: a_h against b_h and b_l
            #pragma unroll
            for (int t = 0; t < 4; t++) {
                uint32_t a[4];
                ldsm_x4(a[0], a[1], a[2], a[3],
                        sb + WH_OFF + (aRow + t * 16) * 128 + aCol);
                #pragma unroll
                for (int jj = 0; jj < 4; jj++) {
                    mma_bf16(cacc[t][jj], a, &bh[jj >> 1][(jj & 1) * 2]);
                    mma_bf16(cacc[t][jj], a, &bl[jj >> 1][(jj & 1) * 2]);
                }
            }
            // pass 3: a_l against b_h
            #pragma unroll
            for (int t = 0; t < 4; t++) {
                uint32_t a[4];
                ldsm_x4(a[0], a[1], a[2], a[3],
                        sb + WL_OFF + (aRow + t * 16) * 128 + aCol);
                #pragma unroll
                for (int jj = 0; jj < 4; jj++)
                    mma_bf16(cacc[t][jj], a, &bh[jj >> 1][(jj & 1) * 2]);
            }
        }

        __syncthreads();
        if (j + 2 < NPOS) issue_pos(j + 2, slot);
    }

    // ---------------- epilogue ----------------
    __syncthreads();   // done reading pipeline smem
    float* stag = (float*)smem;    // [128 m][EPI_PITCH np]

    #pragma unroll
    for (int i = 0; i < 4; i++) {
        const int np0 = npwarp + i * 16 + (l >> 2);
        #pragma unroll
        for (int jj = 0; jj < 4; jj++) {
            const int m0 = mwarp + jj * 8 + (l & 3) * 2;
            stag[(size_t)m0 * EPI_PITCH + np0]           = cacc[i][jj][0];
            stag[(size_t)(m0 + 1) * EPI_PITCH + np0]     = cacc[i][jj][1];
            stag[(size_t)m0 * EPI_PITCH + np0 + 8]       = cacc[i][jj][2];
            stag[(size_t)(m0 + 1) * EPI_PITCH + np0 + 8] = cacc[i][jj][3];
        }
    }
    __syncthreads();

    // This CTA covers a single gate: np range [bm*256, bm*256+256)
    const int gate = bm >> 2;
    const int d0 = (bm & 3) * 256;
    float* plane = g_u + (size_t)gate * PLANE;

    for (int idx = tid; idx < 128 * 256; idx += 512) {
        const int m = idx >> 8;
        const int np = idx & 255;
        float v = stag[(size_t)m * EPI_PITCH + np];
        if (gate) {
            const float bv = bias[(gate - 1) * D_SZ + d0 + np];
            v = 1.0f / (1.0f + __expf(-(v + bv)));
        }
        plane[(size_t)(bn * 128 + m) * D_SZ + d0 + np] = v;
    }
}

// ---------------------------------------------------------------------------
// Segmented scan.  c_t = g1*c + u0*(1-g1)  (affine in c)
// ---------------------------------------------------------------------------
__global__ __launch_bounds__(256)
void scan_seg_kernel() {
    const int gid = blockIdx.x * blockDim.x + threadIdx.x;  // NSEG * 16384
    const int lanei = gid & 16383;
    const int s = gid >> 14;
    const float* __restrict__ u0 = g_u;
    const float* __restrict__ g1 = g_u + PLANE;
    size_t o = (size_t)s * SEG_T * 16384 + lanei;
    float A = 1.0f, Bc = 0.0f;
    #pragma unroll 8
    for (int t = 0; t < SEG_T; t++) {
        const float a = g1[o];
        const float u = u0[o];
        Bc = Bc * a + u * (1.0f - a);
        A *= a;
        o += 16384;
    }
    g_segAx[gid] = A;
    g_segBx[gid] = Bc;
}

__global__ __launch_bounds__(256)
void scan_prefix_kernel(const float* __restrict__ c0) {
    const int lanei = blockIdx.x * blockDim.x + threadIdx.x;  // 16384
    float c = c0[lanei];
    #pragma unroll
    for (int s = 0; s < NSEG; s++) {
        g_cst[s * 16384 + lanei] = c;
        c = g_segAx[s * 16384 + lanei] * c + g_segBx[s * 16384 + lanei];
    }
}

__global__ __launch_bounds__(256)
void scan_out_kernel(const float* __restrict__ x, float* __restrict__ out) {
    const int gid = blockIdx.x * blockDim.x + threadIdx.x;  // NSEG * 16384
    const int lanei = gid & 16383;
    const int s = gid >> 14;
    const float* __restrict__ u0 = g_u;
    const float* __restrict__ g1 = g_u + PLANE;
    const float* __restrict__ g2 = g_u + 2ull * PLANE;
    float c = g_cst[s * 16384 + lanei];
    size_t o = (size_t)s * SEG_T * 16384 + lanei;
    #pragma unroll 4
    for (int t = 0; t < SEG_T; t++) {
        const float u = u0[o];
        const float a = g1[o];
        const float b = g2[o];
        const float xv = x[o];
        c = (c - u) * a + u;
        out[o] = (tanhf(c) - xv) * b + xv;
        o += 16384;
    }
    if (s == NSEG - 1) out[PLANE + lanei] = c;  // c_last
}

// ---------------------------------------------------------------------------
// Launch
// ---------------------------------------------------------------------------
extern "C" void kernel_launch(void* const* d_in, const int* in_sizes, int n_in,
                              void* d_out, int out_size) {
    const float* x      = (const float*)d_in[0];  // (L,B,D)
    const float* weight = (const float*)d_in[1];  // (D, 3D)
    const float* bias   = (const float*)d_in[2];  // (2D)
    const float* c0     = (const float*)d_in[3];  // (B,D)
    float* out = (float*)d_out;                   // h then c_last

    conv_x_kernel<<<(M_X * 128) / 256, 256>>>(x);
    conv_w_kernel<<<(N_W * 512) / 256, 256>>>(weight);

    static int smem_set = 0;
    if (!smem_set) {
        cudaFuncSetAttribute(sru_gemm_mma, cudaFuncAttributeMaxDynamicSharedMemorySize,
                             SMEM_TOTAL);
        smem_set = 1;
    }
    sru_gemm_mma<<<dim3(M_X / 128, N_W / 256), 512, SMEM_TOTAL>>>(bias);

    scan_seg_kernel<<<(NSEG * 16384) / 256, 256>>>();
    scan_prefix_kernel<<<16384 / 256, 256>>>(c0);
    scan_out_kernel<<<(NSEG * 16384) / 256, 256>>>(x, out);
}

// round 7
// speedup vs baseline: 4.2702x; 1.3729x over previous
#include <cuda_runtime.h>
#include <cuda_fp16.h>
#include <cstdint>
#include <math.h>

// ---------------------------------------------------------------------------
// Problem constants
// ---------------------------------------------------------------------------
#define L_SEQ 1024
#define B_SZ  16
#define D_SZ  1024
#define M_X   (L_SEQ * B_SZ)        // 16384 x-rows
#define N_W   3072                  // weight rows (gate-major permuted)
#define NPOS  16                    // physical k-positions (chunks of 64)
#define PLANE ((size_t)M_X * D_SZ)  // 16,777,216

#define NSEG 16
#define SEG_T (L_SEQ / NSEG)        // 64

// ---------------------------------------------------------------------------
// Scratch (__device__ globals: allocation-free)
// ---------------------------------------------------------------------------
// Packed, pre-swizzled fp16 operands: [chunk][row][128B swizzled].
// X: chunks 0..15 = hi, 16..31 = lo.  W: chunks 0..15 (fp16-rounded only).
__device__ __align__(1024) __half g_xc[(size_t)M_X * 2048];   // 64 MiB
__device__ __align__(1024) __half g_wc[(size_t)N_W * 1024];   // 6 MiB
// GEMM output planes: u0, sigmoid(u1+b1), sigmoid(u2+b2), each [M_X, D]
__device__ float g_u[3ull * PLANE];                            // 201 MB
// Segmented-scan scratch
__device__ float g_segAx[NSEG * B_SZ * D_SZ];
__device__ float g_segBx[NSEG * B_SZ * D_SZ];
__device__ float g_cst  [NSEG * B_SZ * D_SZ];

// ---------------------------------------------------------------------------
// helpers
// ---------------------------------------------------------------------------
__device__ __forceinline__ uint32_t smem_u32(const void* p) {
    return (uint32_t)__cvta_generic_to_shared(p);
}
__device__ __forceinline__ void cp_async16(uint32_t dst, const void* src) {
    asm volatile("cp.async.cg.shared.global [%0], [%1], 16;" :: "r"(dst), "l"(src));
}
__device__ __forceinline__ void cp_commit() {
    asm volatile("cp.async.commit_group;");
}
template <int N>
__device__ __forceinline__ void cp_wait() {
    asm volatile("cp.async.wait_group %0;" :: "n"(N));
}
__device__ __forceinline__ void ldsm_x4(uint32_t& r0, uint32_t& r1, uint32_t& r2,
                                        uint32_t& r3, uint32_t addr) {
    asm volatile("ldmatrix.sync.aligned.m8n8.x4.shared.b16 {%0,%1,%2,%3}, [%4];"
                 : "=r"(r0), "=r"(r1), "=r"(r2), "=r"(r3) : "r"(addr));
}
__device__ __forceinline__ void mma_fp16(float* d, const uint32_t* a, const uint32_t* b) {
    asm volatile(
        "mma.sync.aligned.m16n8k16.row.col.f32.f16.f16.f32 "
        "{%0,%1,%2,%3}, {%4,%5,%6,%7}, {%8,%9}, {%0,%1,%2,%3};"
        : "+f"(d[0]), "+f"(d[1]), "+f"(d[2]), "+f"(d[3])
        : "r"(a[0]), "r"(a[1]), "r"(a[2]), "r"(a[3]), "r"(b[0]), "r"(b[1]));
}
__device__ __forceinline__ uint32_t pack_h2(float a, float b) {
    __half2 h = __floats2half2_rn(a, b);
    return *reinterpret_cast<uint32_t*>(&h);
}

// ---------------------------------------------------------------------------
// conv_x: X[m][k] fp32 -> packed swizzled fp16 hi/lo tiles
// byte addr = ((chunk*M_X + m)*128) + (2*(k%64) XOR ((m&7)<<4))
// ---------------------------------------------------------------------------
__global__ __launch_bounds__(256)
void conv_x_kernel(const float* __restrict__ X) {
    int gid = blockIdx.x * blockDim.x + threadIdx.x;   // M_X * 128 threads
    int m  = gid >> 7;
    int k  = (gid & 127) * 8;

    const float4* xp = reinterpret_cast<const float4*>(X + (size_t)m * 1024 + k);
    float4 x0 = xp[0];
    float4 x1 = xp[1];
    float v[8] = {x0.x, x0.y, x0.z, x0.w, x1.x, x1.y, x1.z, x1.w};
    float h[8], l[8];
    #pragma unroll
    for (int i = 0; i < 8; i++) {
        h[i] = __half2float(__float2half_rn(v[i]));
        l[i] = v[i] - h[i];
    }

    uint4 hv, lv;
    hv.x = pack_h2(h[0], h[1]); hv.y = pack_h2(h[2], h[3]);
    hv.z = pack_h2(h[4], h[5]); hv.w = pack_h2(h[6], h[7]);
    lv.x = pack_h2(l[0], l[1]); lv.y = pack_h2(l[2], l[3]);
    lv.z = pack_h2(l[4], l[5]); lv.w = pack_h2(l[6], l[7]);

    int chunk = k >> 6;
    uint32_t b = (uint32_t)(k & 63) * 2;
    uint32_t sw = b ^ (((uint32_t)m & 7u) << 4);
    char* base = (char*)g_xc;
    *reinterpret_cast<uint4*>(base + ((size_t)chunk * M_X + m) * 128 + sw) = hv;
    *reinterpret_cast<uint4*>(base + ((size_t)(chunk + 16) * M_X + m) * 128 + sw) = lv;
}

// ---------------------------------------------------------------------------
// conv_w: W[k][3d+gate] fp32 -> packed swizzled fp16 (hi only), rows
// n' = gate*1024 + d
// ---------------------------------------------------------------------------
__global__ __launch_bounds__(256)
void conv_w_kernel(const float* __restrict__ W) {
    int gid = blockIdx.x * blockDim.x + threadIdx.x;   // N_W * 512 threads
    int np = gid % N_W;
    int k  = (gid / N_W) * 2;

    int gate = np >> 10;
    int d    = np & 1023;
    int col  = 3 * d + gate;

    float w0 = W[(size_t)k * N_W + col];
    float w1 = W[(size_t)(k + 1) * N_W + col];

    int chunk = k >> 6;
    uint32_t b = (uint32_t)(k & 63) * 2;
    uint32_t sw = b ^ (((uint32_t)np & 7u) << 4);
    char* base = (char*)g_wc;
    *reinterpret_cast<uint32_t*>(base + ((size_t)chunk * N_W + np) * 128 + sw) = pack_h2(w0, w1);
}

// ---------------------------------------------------------------------------
// mma.sync GEMM: C[np][m] = sum_k Wh[np][k] * (Xh+Xl)[m][k]  (fp16 2-term)
// CTA tile 256(np) x 128(m) x 64(k); 512 threads = 16 warps (4 np x 4 m).
// Per k-position: load Wh(32K)+Xh(16K)+Xl(16K) once; A fragments shared by
// both passes. 3-stage x 64KB cp.async pipeline.
// ---------------------------------------------------------------------------
#define WH_OFF 0
#define XH_OFF 32768
#define XL_OFF 49152
#define STAGE_BYTES 65536        // 64 KB
#define STAGES 3
#define SMEM_TOTAL (STAGES * STAGE_BYTES)   // 196608
#define EPI_PITCH 264            // floats per staging row (256 + pad)

__global__ __launch_bounds__(512, 1)
void sru_gemm_mma(const float* __restrict__ bias) {
    extern __shared__ char smem[];
    const uint32_t sbase = smem_u32(smem);
    const int tid = threadIdx.x;
    const int wid = tid >> 5;
    const int l = tid & 31;

    const int bn = blockIdx.x;    // m tiles (128)
    const int bm = blockIdx.y;    // np tiles (12)

    const int npwarp = (wid & 3) * 64;
    const int mwarp  = (wid >> 2) * 32;

    // ldmatrix per-lane addressing constants
    const uint32_t swz = (uint32_t)(l & 7) << 4;
    const uint32_t aRow = npwarp + (l & 15);
    const uint32_t aHalf = (uint32_t)(l >> 4) << 4;     // 0 or 16
    const uint32_t bRow = mwarp + (l & 7) + ((l & 16) >> 1);
    const uint32_t bHalf = (uint32_t)(l & 8) << 1;      // 0 or 16

    // cp.async sources for this CTA
    const char* aSrcBase = (const char*)g_wc + (size_t)bm * 256 * 128;
    const char* bSrcBase = (const char*)g_xc + (size_t)bn * 128 * 128;

    float cacc[4][4][4];
    #pragma unroll
    for (int i = 0; i < 4; i++)
        #pragma unroll
        for (int j = 0; j < 4; j++)
            #pragma unroll
            for (int r = 0; r < 4; r++) cacc[i][j][r] = 0.0f;

    // Load one physical k-position: Wh (32KB), Xh, Xl (16KB each)
    auto issue_pos = [&](int kc, int slot) {
        const uint32_t sb = sbase + slot * STAGE_BYTES;
        const char* wh = aSrcBase + (size_t)kc * N_W * 128;
        const char* xh = bSrcBase + (size_t)kc * M_X * 128;
        const char* xl = bSrcBase + (size_t)(kc + 16) * M_X * 128;
        #pragma unroll
        for (int r = 0; r < 4; r++) {
            int off = (tid + r * 512) * 16;
            cp_async16(sb + WH_OFF + off, wh + off);
        }
        #pragma unroll
        for (int r = 0; r < 2; r++) {
            int off = (tid + r * 512) * 16;
            cp_async16(sb + XH_OFF + off, xh + off);
        }
        #pragma unroll
        for (int r = 0; r < 2; r++) {
            int off = (tid + r * 512) * 16;
            cp_async16(sb + XL_OFF + off, xl + off);
        }
        cp_commit();
    };

    issue_pos(0, 0);
    issue_pos(1, 1);

    for (int j = 0; j < NPOS; j++) {
        const int slot = j % 3;
        cp_wait<1>();
        __syncthreads();
        // Safe: slot (j+2)%3 was last read during compute of j-1, and every
        // warp has passed that compute to reach the barrier above.
        if (j + 2 < NPOS) issue_pos(j + 2, (j + 2) % 3);

        const uint32_t sb = sbase + slot * STAGE_BYTES;

        #pragma unroll
        for (int ks = 0; ks < 4; ks++) {
            const uint32_t kb = ks * 32;
            const uint32_t aCol = (kb + aHalf) ^ swz;
            const uint32_t bCol = (kb + bHalf) ^ swz;

            uint32_t bh[2][4], bl[2][4];
            #pragma unroll
            for (int g = 0; g < 2; g++) {
                ldsm_x4(bh[g][0], bh[g][1], bh[g][2], bh[g][3],
                        sb + XH_OFF + (bRow + g * 16) * 128 + bCol);
                ldsm_x4(bl[g][0], bl[g][1], bl[g][2], bl[g][3],
                        sb + XL_OFF + (bRow + g * 16) * 128 + bCol);
            }
            #pragma unroll
            for (int t = 0; t < 4; t++) {
                uint32_t a[4];
                ldsm_x4(a[0], a[1], a[2], a[3],
                        sb + WH_OFF + (aRow + t * 16) * 128 + aCol);
                #pragma unroll
                for (int jj = 0; jj < 4; jj++) {
                    mma_fp16(cacc[t][jj], a, &bh[jj >> 1][(jj & 1) * 2]);
                    mma_fp16(cacc[t][jj], a, &bl[jj >> 1][(jj & 1) * 2]);
                }
            }
        }
    }

    // ---------------- epilogue ----------------
    __syncthreads();   // done reading pipeline smem
    float* stag = (float*)smem;    // [128 m][EPI_PITCH np]

    #pragma unroll
    for (int i = 0; i < 4; i++) {
        const int np0 = npwarp + i * 16 + (l >> 2);
        #pragma unroll
        for (int jj = 0; jj < 4; jj++) {
            const int m0 = mwarp + jj * 8 + (l & 3) * 2;
            stag[(size_t)m0 * EPI_PITCH + np0]           = cacc[i][jj][0];
            stag[(size_t)(m0 + 1) * EPI_PITCH + np0]     = cacc[i][jj][1];
            stag[(size_t)m0 * EPI_PITCH + np0 + 8]       = cacc[i][jj][2];
            stag[(size_t)(m0 + 1) * EPI_PITCH + np0 + 8] = cacc[i][jj][3];
        }
    }
    __syncthreads();

    // This CTA covers a single gate: np range [bm*256, bm*256+256)
    const int gate = bm >> 2;
    const int d0 = (bm & 3) * 256;
    float* plane = g_u + (size_t)gate * PLANE;

    for (int idx = tid; idx < 128 * 256; idx += 512) {
        const int m = idx >> 8;
        const int np = idx & 255;
        float v = stag[(size_t)m * EPI_PITCH + np];
        if (gate) {
            const float bv = bias[(gate - 1) * D_SZ + d0 + np];
            v = 1.0f / (1.0f + __expf(-(v + bv)));
        }
        plane[(size_t)(bn * 128 + m) * D_SZ + d0 + np] = v;
    }
}

// ---------------------------------------------------------------------------
// Segmented scan.  c_t = g1*c + u0*(1-g1)  (affine in c)
// ---------------------------------------------------------------------------
__global__ __launch_bounds__(256)
void scan_seg_kernel() {
    const int gid = blockIdx.x * blockDim.x + threadIdx.x;  // NSEG * 16384
    const int lanei = gid & 16383;
    const int s = gid >> 14;
    const float* __restrict__ u0 = g_u;
    const float* __restrict__ g1 = g_u + PLANE;
    size_t o = (size_t)s * SEG_T * 16384 + lanei;
    float A = 1.0f, Bc = 0.0f;
    #pragma unroll 8
    for (int t = 0; t < SEG_T; t++) {
        const float a = g1[o];
        const float u = u0[o];
        Bc = Bc * a + u * (1.0f - a);
        A *= a;
        o += 16384;
    }
    g_segAx[gid] = A;
    g_segBx[gid] = Bc;
}

__global__ __launch_bounds__(256)
void scan_prefix_kernel(const float* __restrict__ c0) {
    const int lanei = blockIdx.x * blockDim.x + threadIdx.x;  // 16384
    float c = c0[lanei];
    #pragma unroll
    for (int s = 0; s < NSEG; s++) {
        g_cst[s * 16384 + lanei] = c;
        c = g_segAx[s * 16384 + lanei] * c + g_segBx[s * 16384 + lanei];
    }
}

__global__ __launch_bounds__(256)
void scan_out_kernel(const float* __restrict__ x, float* __restrict__ out) {
    const int gid = blockIdx.x * blockDim.x + threadIdx.x;  // NSEG * 16384
    const int lanei = gid & 16383;
    const int s = gid >> 14;
    const float* __restrict__ u0 = g_u;
    const float* __restrict__ g1 = g_u + PLANE;
    const float* __restrict__ g2 = g_u + 2ull * PLANE;
    float c = g_cst[s * 16384 + lanei];
    size_t o = (size_t)s * SEG_T * 16384 + lanei;
    #pragma unroll 4
    for (int t = 0; t < SEG_T; t++) {
        const float u = u0[o];
        const float a = g1[o];
        const float b = g2[o];
        const float xv = x[o];
        c = (c - u) * a + u;
        out[o] = (tanhf(c) - xv) * b + xv;
        o += 16384;
    }
    if (s == NSEG - 1) out[PLANE + lanei] = c;  // c_last
}

// ---------------------------------------------------------------------------
// Launch
// ---------------------------------------------------------------------------
extern "C" void kernel_launch(void* const* d_in, const int* in_sizes, int n_in,
                              void* d_out, int out_size) {
    const float* x      = (const float*)d_in[0];  // (L,B,D)
    const float* weight = (const float*)d_in[1];  // (D, 3D)
    const float* bias   = (const float*)d_in[2];  // (2D)
    const float* c0     = (const float*)d_in[3];  // (B,D)
    float* out = (float*)d_out;                   // h then c_last

    conv_x_kernel<<<(M_X * 128) / 256, 256>>>(x);
    conv_w_kernel<<<(N_W * 512) / 256, 256>>>(weight);

    static int smem_set = 0;
    if (!smem_set) {
        cudaFuncSetAttribute(sru_gemm_mma, cudaFuncAttributeMaxDynamicSharedMemorySize,
                             SMEM_TOTAL);
        smem_set = 1;
    }
    sru_gemm_mma<<<dim3(M_X / 128, N_W / 256), 512, SMEM_TOTAL>>>(bias);

    scan_seg_kernel<<<(NSEG * 16384) / 256, 256>>>();
    scan_prefix_kernel<<<16384 / 256, 256>>>(c0);
    scan_out_kernel<<<(NSEG * 16384) / 256, 256>>>(x, out);
}

// round 8
// speedup vs baseline: 6.1585x; 1.4422x over previous
#include <cuda_runtime.h>
#include <cuda_fp16.h>
#include <cstdint>
#include <math.h>

// ---------------------------------------------------------------------------
// Problem constants
// ---------------------------------------------------------------------------
#define L_SEQ 1024
#define B_SZ  16
#define D_SZ  1024
#define M_X   (L_SEQ * B_SZ)        // 16384 x-rows
#define N_W   3072                  // weight rows (gate-major permuted)
#define NPOS  16                    // physical k-positions (chunks of 64)
#define PLANE ((size_t)M_X * D_SZ)  // 16,777,216

#define NSEG 16
#define SEG_T (L_SEQ / NSEG)        // 64

// ---------------------------------------------------------------------------
// Scratch (__device__ globals: allocation-free)
// ---------------------------------------------------------------------------
// Packed, pre-swizzled fp16 operands: [chunk][row][128B swizzled].
__device__ __align__(1024) __half g_xc[(size_t)M_X * 1024];   // 32 MiB
__device__ __align__(1024) __half g_wc[(size_t)N_W * 1024];   // 6 MiB
// GEMM output planes: u0, sigmoid(u1+b1), sigmoid(u2+b2), each [M_X, D]
__device__ float g_u[3ull * PLANE];                            // 201 MB
// Segmented-scan scratch
__device__ float g_segAx[NSEG * B_SZ * D_SZ];
__device__ float g_segBx[NSEG * B_SZ * D_SZ];
__device__ float g_cst  [NSEG * B_SZ * D_SZ];

// ---------------------------------------------------------------------------
// helpers
// ---------------------------------------------------------------------------
__device__ __forceinline__ uint32_t smem_u32(const void* p) {
    return (uint32_t)__cvta_generic_to_shared(p);
}
__device__ __forceinline__ void cp_async16(uint32_t dst, const void* src) {
    asm volatile("cp.async.cg.shared.global [%0], [%1], 16;" :: "r"(dst), "l"(src));
}
__device__ __forceinline__ void cp_commit() {
    asm volatile("cp.async.commit_group;");
}
template <int N>
__device__ __forceinline__ void cp_wait() {
    asm volatile("cp.async.wait_group %0;" :: "n"(N));
}
__device__ __forceinline__ void ldsm_x4(uint32_t& r0, uint32_t& r1, uint32_t& r2,
                                        uint32_t& r3, uint32_t addr) {
    asm volatile("ldmatrix.sync.aligned.m8n8.x4.shared.b16 {%0,%1,%2,%3}, [%4];"
                 : "=r"(r0), "=r"(r1), "=r"(r2), "=r"(r3) : "r"(addr));
}
__device__ __forceinline__ void mma_fp16(float* d, const uint32_t* a, const uint32_t* b) {
    asm volatile(
        "mma.sync.aligned.m16n8k16.row.col.f32.f16.f16.f32 "
        "{%0,%1,%2,%3}, {%4,%5,%6,%7}, {%8,%9}, {%0,%1,%2,%3};"
        : "+f"(d[0]), "+f"(d[1]), "+f"(d[2]), "+f"(d[3])
        : "r"(a[0]), "r"(a[1]), "r"(a[2]), "r"(a[3]), "r"(b[0]), "r"(b[1]));
}
__device__ __forceinline__ uint32_t pack_h2(float a, float b) {
    __half2 h = __floats2half2_rn(a, b);
    return *reinterpret_cast<uint32_t*>(&h);
}

// ---------------------------------------------------------------------------
// conv_x: X[m][k] fp32 -> packed swizzled fp16 tiles
// byte addr = ((chunk*M_X + m)*128) + (2*(k%64) XOR ((m&7)<<4))
// ---------------------------------------------------------------------------
__global__ __launch_bounds__(256)
void conv_x_kernel(const float* __restrict__ X) {
    int gid = blockIdx.x * blockDim.x + threadIdx.x;   // M_X * 128 threads
    int m  = gid >> 7;
    int k  = (gid & 127) * 8;

    const float4* xp = reinterpret_cast<const float4*>(X + (size_t)m * 1024 + k);
    float4 x0 = xp[0];
    float4 x1 = xp[1];

    uint4 hv;
    hv.x = pack_h2(x0.x, x0.y); hv.y = pack_h2(x0.z, x0.w);
    hv.z = pack_h2(x1.x, x1.y); hv.w = pack_h2(x1.z, x1.w);

    int chunk = k >> 6;
    uint32_t b = (uint32_t)(k & 63) * 2;
    uint32_t sw = b ^ (((uint32_t)m & 7u) << 4);
    char* base = (char*)g_xc;
    *reinterpret_cast<uint4*>(base + ((size_t)chunk * M_X + m) * 128 + sw) = hv;
}

// ---------------------------------------------------------------------------
// conv_w: W[k][3d+gate] fp32 -> packed swizzled fp16, rows n' = gate*1024+d
// ---------------------------------------------------------------------------
__global__ __launch_bounds__(256)
void conv_w_kernel(const float* __restrict__ W) {
    int gid = blockIdx.x * blockDim.x + threadIdx.x;   // N_W * 512 threads
    int np = gid % N_W;
    int k  = (gid / N_W) * 2;

    int gate = np >> 10;
    int d    = np & 1023;
    int col  = 3 * d + gate;

    float w0 = W[(size_t)k * N_W + col];
    float w1 = W[(size_t)(k + 1) * N_W + col];

    int chunk = k >> 6;
    uint32_t b = (uint32_t)(k & 63) * 2;
    uint32_t sw = b ^ (((uint32_t)np & 7u) << 4);
    char* base = (char*)g_wc;
    *reinterpret_cast<uint32_t*>(base + ((size_t)chunk * N_W + np) * 128 + sw) = pack_h2(w0, w1);
}

// ---------------------------------------------------------------------------
// mma.sync GEMM: C[np][m] = sum_k W[np][k] * X[m][k]  (fp16 single pass)
// CTA tile 256(np) x 128(m) x 64(k); 512 threads = 16 warps (4 np x 4 m).
// 4-stage x 48KB cp.async pipeline over 16 k-positions.
// ---------------------------------------------------------------------------
#define WH_OFF 0
#define XH_OFF 32768
#define STAGE_BYTES 49152        // 48 KB
#define STAGES 4
#define SMEM_TOTAL (STAGES * STAGE_BYTES)   // 196608
#define EPI_PITCH 264            // floats per staging row (256 + pad)

__global__ __launch_bounds__(512, 1)
void sru_gemm_mma(const float* __restrict__ bias) {
    extern __shared__ char smem[];
    const uint32_t sbase = smem_u32(smem);
    const int tid = threadIdx.x;
    const int wid = tid >> 5;
    const int l = tid & 31;

    const int bn = blockIdx.x;    // m tiles (128)
    const int bm = blockIdx.y;    // np tiles (12)

    const int npwarp = (wid & 3) * 64;
    const int mwarp  = (wid >> 2) * 32;

    // ldmatrix per-lane addressing constants
    const uint32_t swz = (uint32_t)(l & 7) << 4;
    const uint32_t aRow = npwarp + (l & 15);
    const uint32_t aHalf = (uint32_t)(l >> 4) << 4;     // 0 or 16
    const uint32_t bRow = mwarp + (l & 7) + ((l & 16) >> 1);
    const uint32_t bHalf = (uint32_t)(l & 8) << 1;      // 0 or 16

    // cp.async sources for this CTA
    const char* aSrcBase = (const char*)g_wc + (size_t)bm * 256 * 128;
    const char* bSrcBase = (const char*)g_xc + (size_t)bn * 128 * 128;

    float cacc[4][4][4];
    #pragma unroll
    for (int i = 0; i < 4; i++)
        #pragma unroll
        for (int j = 0; j < 4; j++)
            #pragma unroll
            for (int r = 0; r < 4; r++) cacc[i][j][r] = 0.0f;

    // Load one physical k-position: W (32KB), X (16KB)
    auto issue_pos = [&](int kc, int slot) {
        const uint32_t sb = sbase + slot * STAGE_BYTES;
        const char* wh = aSrcBase + (size_t)kc * N_W * 128;
        const char* xh = bSrcBase + (size_t)kc * M_X * 128;
        #pragma unroll
        for (int r = 0; r < 4; r++) {
            int off = (tid + r * 512) * 16;
            cp_async16(sb + WH_OFF + off, wh + off);
        }
        #pragma unroll
        for (int r = 0; r < 2; r++) {
            int off = (tid + r * 512) * 16;
            cp_async16(sb + XH_OFF + off, xh + off);
        }
        cp_commit();
    };

    issue_pos(0, 0);
    issue_pos(1, 1);
    issue_pos(2, 2);

    for (int j = 0; j < NPOS; j++) {
        const int slot = j & 3;
        cp_wait<2>();
        __syncthreads();
        // Safe: slot (j+3)&3 == (j-1)&3 was last read during compute of j-1,
        // and every warp has passed that compute to reach the barrier above.
        if (j + 3 < NPOS) issue_pos(j + 3, (j + 3) & 3);

        const uint32_t sb = sbase + slot * STAGE_BYTES;

        #pragma unroll
        for (int ks = 0; ks < 4; ks++) {
            const uint32_t kb = ks * 32;
            const uint32_t aCol = (kb + aHalf) ^ swz;
            const uint32_t bCol = (kb + bHalf) ^ swz;

            uint32_t bh[2][4];
            #pragma unroll
            for (int g = 0; g < 2; g++) {
                ldsm_x4(bh[g][0], bh[g][1], bh[g][2], bh[g][3],
                        sb + XH_OFF + (bRow + g * 16) * 128 + bCol);
            }
            #pragma unroll
            for (int t = 0; t < 4; t++) {
                uint32_t a[4];
                ldsm_x4(a[0], a[1], a[2], a[3],
                        sb + WH_OFF + (aRow + t * 16) * 128 + aCol);
                #pragma unroll
                for (int jj = 0; jj < 4; jj++)
                    mma_fp16(cacc[t][jj], a, &bh[jj >> 1][(jj & 1) * 2]);
            }
        }
    }

    // ---------------- epilogue ----------------
    __syncthreads();   // done reading pipeline smem
    float* stag = (float*)smem;    // [128 m][EPI_PITCH np]

    #pragma unroll
    for (int i = 0; i < 4; i++) {
        const int np0 = npwarp + i * 16 + (l >> 2);
        #pragma unroll
        for (int jj = 0; jj < 4; jj++) {
            const int m0 = mwarp + jj * 8 + (l & 3) * 2;
            stag[(size_t)m0 * EPI_PITCH + np0]           = cacc[i][jj][0];
            stag[(size_t)(m0 + 1) * EPI_PITCH + np0]     = cacc[i][jj][1];
            stag[(size_t)m0 * EPI_PITCH + np0 + 8]       = cacc[i][jj][2];
            stag[(size_t)(m0 + 1) * EPI_PITCH + np0 + 8] = cacc[i][jj][3];
        }
    }
    __syncthreads();

    // This CTA covers a single gate: np range [bm*256, bm*256+256)
    const int gate = bm >> 2;
    const int d0 = (bm & 3) * 256;
    float* plane = g_u + (size_t)gate * PLANE;

    for (int idx = tid; idx < 128 * 256; idx += 512) {
        const int m = idx >> 8;
        const int np = idx & 255;
        float v = stag[(size_t)m * EPI_PITCH + np];
        if (gate) {
            const float bv = bias[(gate - 1) * D_SZ + d0 + np];
            v = 1.0f / (1.0f + __expf(-(v + bv)));
        }
        plane[(size_t)(bn * 128 + m) * D_SZ + d0 + np] = v;
    }
}

// ---------------------------------------------------------------------------
// Segmented scan.  c_t = g1*c + u0*(1-g1)  (affine in c)
// ---------------------------------------------------------------------------
__global__ __launch_bounds__(256)
void scan_seg_kernel() {
    const int gid = blockIdx.x * blockDim.x + threadIdx.x;  // NSEG * 16384
    const int lanei = gid & 16383;
    const int s = gid >> 14;
    const float* __restrict__ u0 = g_u;
    const float* __restrict__ g1 = g_u + PLANE;
    size_t o = (size_t)s * SEG_T * 16384 + lanei;
    float A = 1.0f, Bc = 0.0f;
    #pragma unroll 8
    for (int t = 0; t < SEG_T; t++) {
        const float a = g1[o];
        const float u = u0[o];
        Bc = Bc * a + u * (1.0f - a);
        A *= a;
        o += 16384;
    }
    g_segAx[gid] = A;
    g_segBx[gid] = Bc;
}

__global__ __launch_bounds__(256)
void scan_prefix_kernel(const float* __restrict__ c0) {
    const int lanei = blockIdx.x * blockDim.x + threadIdx.x;  // 16384
    float c = c0[lanei];
    #pragma unroll
    for (int s = 0; s < NSEG; s++) {
        g_cst[s * 16384 + lanei] = c;
        c = g_segAx[s * 16384 + lanei] * c + g_segBx[s * 16384 + lanei];
    }
}

__global__ __launch_bounds__(256)
void scan_out_kernel(const float* __restrict__ x, float* __restrict__ out) {
    const int gid = blockIdx.x * blockDim.x + threadIdx.x;  // NSEG * 16384
    const int lanei = gid & 16383;
    const int s = gid >> 14;
    const float* __restrict__ u0 = g_u;
    const float* __restrict__ g1 = g_u + PLANE;
    const float* __restrict__ g2 = g_u + 2ull * PLANE;
    float c = g_cst[s * 16384 + lanei];
    size_t o = (size_t)s * SEG_T * 16384 + lanei;
    #pragma unroll 4
    for (int t = 0; t < SEG_T; t++) {
        const float u = u0[o];
        const float a = g1[o];
        const float b = g2[o];
        const float xv = x[o];
        c = (c - u) * a + u;
        out[o] = (tanhf(c) - xv) * b + xv;
        o += 16384;
    }
    if (s == NSEG - 1) out[PLANE + lanei] = c;  // c_last
}

// ---------------------------------------------------------------------------
// Launch
// ---------------------------------------------------------------------------
extern "C" void kernel_launch(void* const* d_in, const int* in_sizes, int n_in,
                              void* d_out, int out_size) {
    const float* x      = (const float*)d_in[0];  // (L,B,D)
    const float* weight = (const float*)d_in[1];  // (D, 3D)
    const float* bias   = (const float*)d_in[2];  // (2D)
    const float* c0     = (const float*)d_in[3];  // (B,D)
    float* out = (float*)d_out;                   // h then c_last

    conv_x_kernel<<<(M_X * 128) / 256, 256>>>(x);
    conv_w_kernel<<<(N_W * 512) / 256, 256>>>(weight);

    static int smem_set = 0;
    if (!smem_set) {
        cudaFuncSetAttribute(sru_gemm_mma, cudaFuncAttributeMaxDynamicSharedMemorySize,
                             SMEM_TOTAL);
        smem_set = 1;
    }
    sru_gemm_mma<<<dim3(M_X / 128, N_W / 256), 512, SMEM_TOTAL>>>(bias);

    scan_seg_kernel<<<(NSEG * 16384) / 256, 256>>>();
    scan_prefix_kernel<<<16384 / 256, 256>>>(c0);
    scan_out_kernel<<<(NSEG * 16384) / 256, 256>>>(x, out);
}

// round 9
// speedup vs baseline: 6.5579x; 1.0648x over previous
#include <cuda_runtime.h>
#include <cuda_fp16.h>
#include <cstdint>
#include <math.h>

// ---------------------------------------------------------------------------
// Problem constants
// ---------------------------------------------------------------------------
#define L_SEQ 1024
#define B_SZ  16
#define D_SZ  1024
#define M_X   (L_SEQ * B_SZ)        // 16384 x-rows
#define N_W   3072                  // weight rows (gate-major permuted)
#define NPOS  16                    // physical k-positions (chunks of 64)
#define PLANE ((size_t)M_X * D_SZ)  // 16,777,216

#define NSEG 16
#define SEG_T (L_SEQ / NSEG)        // 64

// ---------------------------------------------------------------------------
// Scratch (__device__ globals: allocation-free)
// ---------------------------------------------------------------------------
// Packed, pre-swizzled fp16 operands: [chunk][row][128B swizzled].
__device__ __align__(1024) __half g_xc[(size_t)M_X * 1024];   // 32 MiB
__device__ __align__(1024) __half g_wc[(size_t)N_W * 1024];   // 6 MiB
// GEMM outputs: u0 fp32 plane; g1, g2 fp16 planes
__device__ float  g_u0[PLANE];                                 // 67 MB
__device__ __half g_g1[PLANE];                                 // 33.5 MB
__device__ __half g_g2[PLANE];                                 // 33.5 MB
// Segmented-scan scratch
__device__ float g_segAx[NSEG * B_SZ * D_SZ];
__device__ float g_segBx[NSEG * B_SZ * D_SZ];
__device__ float g_cst  [NSEG * B_SZ * D_SZ];

// ---------------------------------------------------------------------------
// helpers
// ---------------------------------------------------------------------------
__device__ __forceinline__ uint32_t smem_u32(const void* p) {
    return (uint32_t)__cvta_generic_to_shared(p);
}
__device__ __forceinline__ void cp_async16(uint32_t dst, const void* src) {
    asm volatile("cp.async.cg.shared.global [%0], [%1], 16;" :: "r"(dst), "l"(src));
}
__device__ __forceinline__ void cp_commit() {
    asm volatile("cp.async.commit_group;");
}
template <int N>
__device__ __forceinline__ void cp_wait() {
    asm volatile("cp.async.wait_group %0;" :: "n"(N));
}
__device__ __forceinline__ void ldsm_x4(uint32_t& r0, uint32_t& r1, uint32_t& r2,
                                        uint32_t& r3, uint32_t addr) {
    asm volatile("ldmatrix.sync.aligned.m8n8.x4.shared.b16 {%0,%1,%2,%3}, [%4];"
                 : "=r"(r0), "=r"(r1), "=r"(r2), "=r"(r3) : "r"(addr));
}
__device__ __forceinline__ void mma_fp16(float* d, const uint32_t* a, const uint32_t* b) {
    asm volatile(
        "mma.sync.aligned.m16n8k16.row.col.f32.f16.f16.f32 "
        "{%0,%1,%2,%3}, {%4,%5,%6,%7}, {%8,%9}, {%0,%1,%2,%3};"
        : "+f"(d[0]), "+f"(d[1]), "+f"(d[2]), "+f"(d[3])
        : "r"(a[0]), "r"(a[1]), "r"(a[2]), "r"(a[3]), "r"(b[0]), "r"(b[1]));
}
__device__ __forceinline__ uint32_t pack_h2(float a, float b) {
    __half2 h = __floats2half2_rn(a, b);
    return *reinterpret_cast<uint32_t*>(&h);
}

// ---------------------------------------------------------------------------
// conv_x: X[m][k] fp32 -> packed swizzled fp16 tiles
// byte addr = ((chunk*M_X + m)*128) + (2*(k%64) XOR ((m&7)<<4))
// ---------------------------------------------------------------------------
__global__ __launch_bounds__(256)
void conv_x_kernel(const float* __restrict__ X) {
    int gid = blockIdx.x * blockDim.x + threadIdx.x;   // M_X * 128 threads
    int m  = gid >> 7;
    int k  = (gid & 127) * 8;

    const float4* xp = reinterpret_cast<const float4*>(X + (size_t)m * 1024 + k);
    float4 x0 = xp[0];
    float4 x1 = xp[1];

    uint4 hv;
    hv.x = pack_h2(x0.x, x0.y); hv.y = pack_h2(x0.z, x0.w);
    hv.z = pack_h2(x1.x, x1.y); hv.w = pack_h2(x1.z, x1.w);

    int chunk = k >> 6;
    uint32_t b = (uint32_t)(k & 63) * 2;
    uint32_t sw = b ^ (((uint32_t)m & 7u) << 4);
    char* base = (char*)g_xc;
    *reinterpret_cast<uint4*>(base + ((size_t)chunk * M_X + m) * 128 + sw) = hv;
}

// ---------------------------------------------------------------------------
// conv_w: W[k][3d+gate] fp32 -> packed swizzled fp16, rows n' = gate*1024+d
// ---------------------------------------------------------------------------
__global__ __launch_bounds__(256)
void conv_w_kernel(const float* __restrict__ W) {
    int gid = blockIdx.x * blockDim.x + threadIdx.x;   // N_W * 512 threads
    int np = gid % N_W;
    int k  = (gid / N_W) * 2;

    int gate = np >> 10;
    int d    = np & 1023;
    int col  = 3 * d + gate;

    float w0 = W[(size_t)k * N_W + col];
    float w1 = W[(size_t)(k + 1) * N_W + col];

    int chunk = k >> 6;
    uint32_t b = (uint32_t)(k & 63) * 2;
    uint32_t sw = b ^ (((uint32_t)np & 7u) << 4);
    char* base = (char*)g_wc;
    *reinterpret_cast<uint32_t*>(base + ((size_t)chunk * N_W + np) * 128 + sw) = pack_h2(w0, w1);
}

// ---------------------------------------------------------------------------
// mma.sync GEMM: C[np][m] = sum_k W[np][k] * X[m][k]  (fp16 single pass)
// CTA tile 256(np) x 128(m) x 128(k-per-stage); 512 threads = 16 warps.
// 2-stage x 96KB cp.async pipeline, 8 macro-iterations of 2 k-positions.
// ---------------------------------------------------------------------------
#define SUB_BYTES 49152          // one k-position: W 32KB + X 16KB
#define W_OFF 0
#define X_OFF 32768
#define STAGE_BYTES (2 * SUB_BYTES)          // 96 KB (2 k-positions)
#define SMEM_TOTAL (2 * STAGE_BYTES)         // 192 KB
#define NITER (NPOS / 2)                     // 8
#define EPI_PITCH 264            // floats per staging row (256 + pad)

__global__ __launch_bounds__(512, 1)
void sru_gemm_mma(const float* __restrict__ bias) {
    extern __shared__ char smem[];
    const uint32_t sbase = smem_u32(smem);
    const int tid = threadIdx.x;
    const int wid = tid >> 5;
    const int l = tid & 31;

    const int bn = blockIdx.x;    // m tiles (128)
    const int bm = blockIdx.y;    // np tiles (12)

    const int npwarp = (wid & 3) * 64;
    const int mwarp  = (wid >> 2) * 32;

    // ldmatrix per-lane addressing constants
    const uint32_t swz = (uint32_t)(l & 7) << 4;
    const uint32_t aRow = npwarp + (l & 15);
    const uint32_t aHalf = (uint32_t)(l >> 4) << 4;     // 0 or 16
    const uint32_t bRow = mwarp + (l & 7) + ((l & 16) >> 1);
    const uint32_t bHalf = (uint32_t)(l & 8) << 1;      // 0 or 16

    // cp.async sources for this CTA
    const char* aSrcBase = (const char*)g_wc + (size_t)bm * 256 * 128;
    const char* bSrcBase = (const char*)g_xc + (size_t)bn * 128 * 128;

    float cacc[4][4][4];
    #pragma unroll
    for (int i = 0; i < 4; i++)
        #pragma unroll
        for (int j = 0; j < 4; j++)
            #pragma unroll
            for (int r = 0; r < 4; r++) cacc[i][j][r] = 0.0f;

    // Load one macro-stage = 2 k-positions (W 64KB, X 32KB total)
    auto issue_stage = [&](int it, int slot) {
        const uint32_t sb = sbase + slot * STAGE_BYTES;
        #pragma unroll
        for (int p = 0; p < 2; p++) {
            const int kc = it * 2 + p;
            const uint32_t pb = sb + p * SUB_BYTES;
            const char* wh = aSrcBase + (size_t)kc * N_W * 128;
            const char* xh = bSrcBase + (size_t)kc * M_X * 128;
            #pragma unroll
            for (int r = 0; r < 4; r++) {
                int off = (tid + r * 512) * 16;
                cp_async16(pb + W_OFF + off, wh + off);
            }
            #pragma unroll
            for (int r = 0; r < 2; r++) {
                int off = (tid + r * 512) * 16;
                cp_async16(pb + X_OFF + off, xh + off);
            }
        }
        cp_commit();
    };

    issue_stage(0, 0);
    issue_stage(1, 1);

    for (int j = 0; j < NITER; j++) {
        const int slot = j & 1;
        cp_wait<1>();
        __syncthreads();

        const uint32_t sb = sbase + slot * STAGE_BYTES;

        #pragma unroll
        for (int p = 0; p < 2; p++) {
            const uint32_t pb = sb + p * SUB_BYTES;
            #pragma unroll
            for (int ks = 0; ks < 4; ks++) {
                const uint32_t kb = ks * 32;
                const uint32_t aCol = (kb + aHalf) ^ swz;
                const uint32_t bCol = (kb + bHalf) ^ swz;

                uint32_t bh[2][4];
                #pragma unroll
                for (int g = 0; g < 2; g++) {
                    ldsm_x4(bh[g][0], bh[g][1], bh[g][2], bh[g][3],
                            pb + X_OFF + (bRow + g * 16) * 128 + bCol);
                }
                #pragma unroll
                for (int t = 0; t < 4; t++) {
                    uint32_t a[4];
                    ldsm_x4(a[0], a[1], a[2], a[3],
                            pb + W_OFF + (aRow + t * 16) * 128 + aCol);
                    #pragma unroll
                    for (int jj = 0; jj < 4; jj++)
                        mma_fp16(cacc[t][jj], a, &bh[jj >> 1][(jj & 1) * 2]);
                }
            }
        }

        __syncthreads();   // all warps done reading this slot
        if (j + 2 < NITER) issue_stage(j + 2, slot);
    }

    // ---------------- epilogue ----------------
    __syncthreads();   // done reading pipeline smem
    float* stag = (float*)smem;    // [128 m][EPI_PITCH np]

    #pragma unroll
    for (int i = 0; i < 4; i++) {
        const int np0 = npwarp + i * 16 + (l >> 2);
        #pragma unroll
        for (int jj = 0; jj < 4; jj++) {
            const int m0 = mwarp + jj * 8 + (l & 3) * 2;
            stag[(size_t)m0 * EPI_PITCH + np0]           = cacc[i][jj][0];
            stag[(size_t)(m0 + 1) * EPI_PITCH + np0]     = cacc[i][jj][1];
            stag[(size_t)m0 * EPI_PITCH + np0 + 8]       = cacc[i][jj][2];
            stag[(size_t)(m0 + 1) * EPI_PITCH + np0 + 8] = cacc[i][jj][3];
        }
    }
    __syncthreads();

    // This CTA covers a single gate: np range [bm*256, bm*256+256)
    const int gate = bm >> 2;
    const int d0 = (bm & 3) * 256;

    if (gate == 0) {
        for (int idx = tid; idx < 128 * 256; idx += 512) {
            const int m = idx >> 8;
            const int np = idx & 255;
            g_u0[(size_t)(bn * 128 + m) * D_SZ + d0 + np] =
                stag[(size_t)m * EPI_PITCH + np];
        }
    } else {
        __half* gplane = (gate == 1) ? g_g1 : g_g2;
        for (int idx = tid; idx < 128 * 256; idx += 512) {
            const int m = idx >> 8;
            const int np = idx & 255;
            float v = stag[(size_t)m * EPI_PITCH + np];
            const float bv = bias[(gate - 1) * D_SZ + d0 + np];
            v = 1.0f / (1.0f + __expf(-(v + bv)));
            gplane[(size_t)(bn * 128 + m) * D_SZ + d0 + np] = __float2half_rn(v);
        }
    }
}

// ---------------------------------------------------------------------------
// Segmented scan.  c_t = g1*c + u0*(1-g1)  (affine in c)
// ---------------------------------------------------------------------------
__global__ __launch_bounds__(256)
void scan_seg_kernel() {
    const int gid = blockIdx.x * blockDim.x + threadIdx.x;  // NSEG * 16384
    const int lanei = gid & 16383;
    const int s = gid >> 14;
    const float*  __restrict__ u0 = g_u0;
    const __half* __restrict__ g1 = g_g1;
    size_t o = (size_t)s * SEG_T * 16384 + lanei;
    float A = 1.0f, Bc = 0.0f;
    #pragma unroll 8
    for (int t = 0; t < SEG_T; t++) {
        const float a = __half2float(g1[o]);
        const float u = u0[o];
        Bc = Bc * a + u * (1.0f - a);
        A *= a;
        o += 16384;
    }
    g_segAx[gid] = A;
    g_segBx[gid] = Bc;
}

__global__ __launch_bounds__(256)
void scan_prefix_kernel(const float* __restrict__ c0) {
    const int lanei = blockIdx.x * blockDim.x + threadIdx.x;  // 16384
    float c = c0[lanei];
    #pragma unroll
    for (int s = 0; s < NSEG; s++) {
        g_cst[s * 16384 + lanei] = c;
        c = g_segAx[s * 16384 + lanei] * c + g_segBx[s * 16384 + lanei];
    }
}

__global__ __launch_bounds__(256)
void scan_out_kernel(const float* __restrict__ x, float* __restrict__ out) {
    const int gid = blockIdx.x * blockDim.x + threadIdx.x;  // NSEG * 16384
    const int lanei = gid & 16383;
    const int s = gid >> 14;
    const float*  __restrict__ u0 = g_u0;
    const __half* __restrict__ g1 = g_g1;
    const __half* __restrict__ g2 = g_g2;
    float c = g_cst[s * 16384 + lanei];
    size_t o = (size_t)s * SEG_T * 16384 + lanei;
    #pragma unroll 4
    for (int t = 0; t < SEG_T; t++) {
        const float u = u0[o];
        const float a = __half2float(g1[o]);
        const float b = __half2float(g2[o]);
        const float xv = x[o];
        c = (c - u) * a + u;
        out[o] = (tanhf(c) - xv) * b + xv;
        o += 16384;
    }
    if (s == NSEG - 1) out[PLANE + lanei] = c;  // c_last
}

// ---------------------------------------------------------------------------
// Launch
// ---------------------------------------------------------------------------
extern "C" void kernel_launch(void* const* d_in, const int* in_sizes, int n_in,
                              void* d_out, int out_size) {
    const float* x      = (const float*)d_in[0];  // (L,B,D)
    const float* weight = (const float*)d_in[1];  // (D, 3D)
    const float* bias   = (const float*)d_in[2];  // (2D)
    const float* c0     = (const float*)d_in[3];  // (B,D)
    float* out = (float*)d_out;                   // h then c_last

    conv_x_kernel<<<(M_X * 128) / 256, 256>>>(x);
    conv_w_kernel<<<(N_W * 512) / 256, 256>>>(weight);

    static int smem_set = 0;
    if (!smem_set) {
        cudaFuncSetAttribute(sru_gemm_mma, cudaFuncAttributeMaxDynamicSharedMemorySize,
                             SMEM_TOTAL);
        smem_set = 1;
    }
    sru_gemm_mma<<<dim3(M_X / 128, N_W / 256), 512, SMEM_TOTAL>>>(bias);

    scan_seg_kernel<<<(NSEG * 16384) / 256, 256>>>();
    scan_prefix_kernel<<<16384 / 256, 256>>>(c0);
    scan_out_kernel<<<(NSEG * 16384) / 256, 256>>>(x, out);
}

// round 10
// speedup vs baseline: 7.3114x; 1.1149x over previous
#include <cuda_runtime.h>
#include <cuda_fp16.h>
#include <cstdint>
#include <math.h>

// ---------------------------------------------------------------------------
// Problem constants
// ---------------------------------------------------------------------------
#define L_SEQ 1024
#define B_SZ  16
#define D_SZ  1024
#define M_X   (L_SEQ * B_SZ)        // 16384 x-rows
#define N_W   3072                  // weight rows (gate-major permuted)
#define NPOS  16                    // physical k-positions (chunks of 64)
#define PLANE ((size_t)M_X * D_SZ)  // 16,777,216

#define NSEG 16
#define SEG_T (L_SEQ / NSEG)        // 64

// ---------------------------------------------------------------------------
// Scratch (__device__ globals: allocation-free)
// ---------------------------------------------------------------------------
// Packed, pre-swizzled fp16 operands: [chunk][row][128B swizzled].
__device__ __align__(1024) __half g_xc[(size_t)M_X * 1024];   // 32 MiB
__device__ __align__(1024) __half g_wc[(size_t)N_W * 1024];   // 6 MiB
// GEMM outputs: u0, g1, g2 all fp16 planes
__device__ __half g_u0[PLANE];                                 // 33.5 MB
__device__ __half g_g1[PLANE];                                 // 33.5 MB
__device__ __half g_g2[PLANE];                                 // 33.5 MB
// Segmented-scan scratch
__device__ float g_segAx[NSEG * B_SZ * D_SZ];
__device__ float g_segBx[NSEG * B_SZ * D_SZ];
__device__ float g_cst  [NSEG * B_SZ * D_SZ];

// ---------------------------------------------------------------------------
// helpers
// ---------------------------------------------------------------------------
__device__ __forceinline__ uint32_t smem_u32(const void* p) {
    return (uint32_t)__cvta_generic_to_shared(p);
}
__device__ __forceinline__ void cp_async16(uint32_t dst, const void* src) {
    asm volatile("cp.async.cg.shared.global [%0], [%1], 16;" :: "r"(dst), "l"(src));
}
__device__ __forceinline__ void cp_commit() {
    asm volatile("cp.async.commit_group;");
}
template <int N>
__device__ __forceinline__ void cp_wait() {
    asm volatile("cp.async.wait_group %0;" :: "n"(N));
}
__device__ __forceinline__ void ldsm_x4(uint32_t& r0, uint32_t& r1, uint32_t& r2,
                                        uint32_t& r3, uint32_t addr) {
    asm volatile("ldmatrix.sync.aligned.m8n8.x4.shared.b16 {%0,%1,%2,%3}, [%4];"
                 : "=r"(r0), "=r"(r1), "=r"(r2), "=r"(r3) : "r"(addr));
}
__device__ __forceinline__ void mma_fp16(float* d, const uint32_t* a, const uint32_t* b) {
    asm volatile(
        "mma.sync.aligned.m16n8k16.row.col.f32.f16.f16.f32 "
        "{%0,%1,%2,%3}, {%4,%5,%6,%7}, {%8,%9}, {%0,%1,%2,%3};"
        : "+f"(d[0]), "+f"(d[1]), "+f"(d[2]), "+f"(d[3])
        : "r"(a[0]), "r"(a[1]), "r"(a[2]), "r"(a[3]), "r"(b[0]), "r"(b[1]));
}
__device__ __forceinline__ uint32_t pack_h2(float a, float b) {
    __half2 h = __floats2half2_rn(a, b);
    return *reinterpret_cast<uint32_t*>(&h);
}

// ---------------------------------------------------------------------------
// conv_x: X[m][k] fp32 -> packed swizzled fp16 tiles
// byte addr = ((chunk*M_X + m)*128) + (2*(k%64) XOR ((m&7)<<4))
// ---------------------------------------------------------------------------
__global__ __launch_bounds__(256)
void conv_x_kernel(const float* __restrict__ X) {
    int gid = blockIdx.x * blockDim.x + threadIdx.x;   // M_X * 128 threads
    int m  = gid >> 7;
    int k  = (gid & 127) * 8;

    const float4* xp = reinterpret_cast<const float4*>(X + (size_t)m * 1024 + k);
    float4 x0 = xp[0];
    float4 x1 = xp[1];

    uint4 hv;
    hv.x = pack_h2(x0.x, x0.y); hv.y = pack_h2(x0.z, x0.w);
    hv.z = pack_h2(x1.x, x1.y); hv.w = pack_h2(x1.z, x1.w);

    int chunk = k >> 6;
    uint32_t b = (uint32_t)(k & 63) * 2;
    uint32_t sw = b ^ (((uint32_t)m & 7u) << 4);
    char* base = (char*)g_xc;
    *reinterpret_cast<uint4*>(base + ((size_t)chunk * M_X + m) * 128 + sw) = hv;
}

// ---------------------------------------------------------------------------
// conv_w: W[k][3d+gate] fp32 -> packed swizzled fp16, rows n' = gate*1024+d
// ---------------------------------------------------------------------------
__global__ __launch_bounds__(256)
void conv_w_kernel(const float* __restrict__ W) {
    int gid = blockIdx.x * blockDim.x + threadIdx.x;   // N_W * 512 threads
    int np = gid % N_W;
    int k  = (gid / N_W) * 2;

    int gate = np >> 10;
    int d    = np & 1023;
    int col  = 3 * d + gate;

    float w0 = W[(size_t)k * N_W + col];
    float w1 = W[(size_t)(k + 1) * N_W + col];

    int chunk = k >> 6;
    uint32_t b = (uint32_t)(k & 63) * 2;
    uint32_t sw = b ^ (((uint32_t)np & 7u) << 4);
    char* base = (char*)g_wc;
    *reinterpret_cast<uint32_t*>(base + ((size_t)chunk * N_W + np) * 128 + sw) = pack_h2(w0, w1);
}

// ---------------------------------------------------------------------------
// mma.sync GEMM: C[np][m] = sum_k W[np][k] * X[m][k]  (fp16 single pass)
// CTA tile 128(np) x 128(m) x 64(k); 256 threads = 8 warps (2 np x 4 m).
// 3-stage x 32KB cp.async pipeline; 96KB smem => 2 CTAs/SM for cross-CTA
// overlap of fills/barriers/epilogue with the other CTA's mma stream.
// ---------------------------------------------------------------------------
#define W_OFF 0
#define X_OFF 16384
#define STAGE_BYTES 32768        // W 16KB + X 16KB
#define STAGES 3
#define SMEM_TOTAL (STAGES * STAGE_BYTES)   // 98304 (96 KB)
#define EPI_PITCH 132            // floats per staging row (128 + pad)

__global__ __launch_bounds__(256, 2)
void sru_gemm_mma(const float* __restrict__ bias) {
    extern __shared__ char smem[];
    const uint32_t sbase = smem_u32(smem);
    const int tid = threadIdx.x;
    const int wid = tid >> 5;
    const int l = tid & 31;

    const int bn = blockIdx.x;    // m tiles (128)
    const int bm = blockIdx.y;    // np tiles (24)

    const int npwarp = (wid & 1) * 64;
    const int mwarp  = (wid >> 1) * 32;

    // ldmatrix per-lane addressing constants
    const uint32_t swz = (uint32_t)(l & 7) << 4;
    const uint32_t aRow = npwarp + (l & 15);
    const uint32_t aHalf = (uint32_t)(l >> 4) << 4;     // 0 or 16
    const uint32_t bRow = mwarp + (l & 7) + ((l & 16) >> 1);
    const uint32_t bHalf = (uint32_t)(l & 8) << 1;      // 0 or 16

    // cp.async sources for this CTA
    const char* aSrcBase = (const char*)g_wc + (size_t)bm * 128 * 128;
    const char* bSrcBase = (const char*)g_xc + (size_t)bn * 128 * 128;

    float cacc[4][4][4];
    #pragma unroll
    for (int i = 0; i < 4; i++)
        #pragma unroll
        for (int j = 0; j < 4; j++)
            #pragma unroll
            for (int r = 0; r < 4; r++) cacc[i][j][r] = 0.0f;

    // Load one k-position: W (16KB) + X (16KB)
    auto issue_pos = [&](int kc, int slot) {
        const uint32_t sb = sbase + slot * STAGE_BYTES;
        const char* wh = aSrcBase + (size_t)kc * N_W * 128;
        const char* xh = bSrcBase + (size_t)kc * M_X * 128;
        #pragma unroll
        for (int r = 0; r < 4; r++) {
            int off = (tid + r * 256) * 16;
            cp_async16(sb + W_OFF + off, wh + off);
        }
        #pragma unroll
        for (int r = 0; r < 4; r++) {
            int off = (tid + r * 256) * 16;
            cp_async16(sb + X_OFF + off, xh + off);
        }
        cp_commit();
    };

    issue_pos(0, 0);
    issue_pos(1, 1);

    for (int j = 0; j < NPOS; j++) {
        const int slot = j % 3;
        cp_wait<1>();
        __syncthreads();
        // Slot (j+2)%3 == (j-1)%3 was last read during compute of j-1; the
        // barrier above proves every warp finished that compute.
        if (j + 2 < NPOS) issue_pos(j + 2, (j + 2) % 3);

        const uint32_t sb = sbase + slot * STAGE_BYTES;

        #pragma unroll
        for (int ks = 0; ks < 4; ks++) {
            const uint32_t kb = ks * 32;
            const uint32_t aCol = (kb + aHalf) ^ swz;
            const uint32_t bCol = (kb + bHalf) ^ swz;

            uint32_t bh[2][4];
            #pragma unroll
            for (int g = 0; g < 2; g++) {
                ldsm_x4(bh[g][0], bh[g][1], bh[g][2], bh[g][3],
                        sb + X_OFF + (bRow + g * 16) * 128 + bCol);
            }
            #pragma unroll
            for (int t = 0; t < 4; t++) {
                uint32_t a[4];
                ldsm_x4(a[0], a[1], a[2], a[3],
                        sb + W_OFF + (aRow + t * 16) * 128 + aCol);
                #pragma unroll
                for (int jj = 0; jj < 4; jj++)
                    mma_fp16(cacc[t][jj], a, &bh[jj >> 1][(jj & 1) * 2]);
            }
        }
    }

    // ---------------- epilogue ----------------
    __syncthreads();   // done reading pipeline smem
    float* stag = (float*)smem;    // [128 m][EPI_PITCH np]  (67.6 KB < 96 KB)

    #pragma unroll
    for (int i = 0; i < 4; i++) {
        const int np0 = npwarp + i * 16 + (l >> 2);
        #pragma unroll
        for (int jj = 0; jj < 4; jj++) {
            const int m0 = mwarp + jj * 8 + (l & 3) * 2;
            stag[(size_t)m0 * EPI_PITCH + np0]           = cacc[i][jj][0];
            stag[(size_t)(m0 + 1) * EPI_PITCH + np0]     = cacc[i][jj][1];
            stag[(size_t)m0 * EPI_PITCH + np0 + 8]       = cacc[i][jj][2];
            stag[(size_t)(m0 + 1) * EPI_PITCH + np0 + 8] = cacc[i][jj][3];
        }
    }
    __syncthreads();

    // This CTA covers a single gate: np range [bm*128, bm*128+128)
    const int gate = bm >> 3;
    const int d0 = (bm & 7) * 128;
    __half* plane = (gate == 0) ? g_u0 : ((gate == 1) ? g_g1 : g_g2);

    // 128 m x 64 half2 stores
    for (int idx = tid; idx < 128 * 64; idx += 256) {
        const int m = idx >> 6;
        const int np2 = (idx & 63) * 2;
        float v0 = stag[(size_t)m * EPI_PITCH + np2];
        float v1 = stag[(size_t)m * EPI_PITCH + np2 + 1];
        if (gate) {
            const float b0 = bias[(gate - 1) * D_SZ + d0 + np2];
            const float b1 = bias[(gate - 1) * D_SZ + d0 + np2 + 1];
            v0 = 1.0f / (1.0f + __expf(-(v0 + b0)));
            v1 = 1.0f / (1.0f + __expf(-(v1 + b1)));
        }
        __half2 hv = __floats2half2_rn(v0, v1);
        *reinterpret_cast<__half2*>(
            &plane[(size_t)(bn * 128 + m) * D_SZ + d0 + np2]) = hv;
    }
}

// ---------------------------------------------------------------------------
// Segmented scan.  c_t = g1*c + u0*(1-g1)  (affine in c)
// ---------------------------------------------------------------------------
__global__ __launch_bounds__(256)
void scan_seg_kernel() {
    const int gid = blockIdx.x * blockDim.x + threadIdx.x;  // NSEG * 16384
    const int lanei = gid & 16383;
    const int s = gid >> 14;
    const __half* __restrict__ u0 = g_u0;
    const __half* __restrict__ g1 = g_g1;
    size_t o = (size_t)s * SEG_T * 16384 + lanei;
    float A = 1.0f, Bc = 0.0f;
    #pragma unroll 8
    for (int t = 0; t < SEG_T; t++) {
        const float a = __half2float(g1[o]);
        const float u = __half2float(u0[o]);
        Bc = Bc * a + u * (1.0f - a);
        A *= a;
        o += 16384;
    }
    g_segAx[gid] = A;
    g_segBx[gid] = Bc;
}

__global__ __launch_bounds__(256)
void scan_prefix_kernel(const float* __restrict__ c0) {
    const int lanei = blockIdx.x * blockDim.x + threadIdx.x;  // 16384
    float c = c0[lanei];
    #pragma unroll
    for (int s = 0; s < NSEG; s++) {
        g_cst[s * 16384 + lanei] = c;
        c = g_segAx[s * 16384 + lanei] * c + g_segBx[s * 16384 + lanei];
    }
}

__global__ __launch_bounds__(256)
void scan_out_kernel(const float* __restrict__ x, float* __restrict__ out) {
    const int gid = blockIdx.x * blockDim.x + threadIdx.x;  // NSEG * 16384
    const int lanei = gid & 16383;
    const int s = gid >> 14;
    const __half* __restrict__ u0 = g_u0;
    const __half* __restrict__ g1 = g_g1;
    const __half* __restrict__ g2 = g_g2;
    float c = g_cst[s * 16384 + lanei];
    size_t o = (size_t)s * SEG_T * 16384 + lanei;
    #pragma unroll 4
    for (int t = 0; t < SEG_T; t++) {
        const float u = __half2float(u0[o]);
        const float a = __half2float(g1[o]);
        const float b = __half2float(g2[o]);
        const float xv = x[o];
        c = (c - u) * a + u;
        out[o] = (tanhf(c) - xv) * b + xv;
        o += 16384;
    }
    if (s == NSEG - 1) out[PLANE + lanei] = c;  // c_last
}

// ---------------------------------------------------------------------------
// Launch
// ---------------------------------------------------------------------------
extern "C" void kernel_launch(void* const* d_in, const int* in_sizes, int n_in,
                              void* d_out, int out_size) {
    const float* x      = (const float*)d_in[0];  // (L,B,D)
    const float* weight = (const float*)d_in[1];  // (D, 3D)
    const float* bias   = (const float*)d_in[2];  // (2D)
    const float* c0     = (const float*)d_in[3];  // (B,D)
    float* out = (float*)d_out;                   // h then c_last

    conv_x_kernel<<<(M_X * 128) / 256, 256>>>(x);
    conv_w_kernel<<<(N_W * 512) / 256, 256>>>(weight);

    static int smem_set = 0;
    if (!smem_set) {
        cudaFuncSetAttribute(sru_gemm_mma, cudaFuncAttributeMaxDynamicSharedMemorySize,
                             SMEM_TOTAL);
        smem_set = 1;
    }
    sru_gemm_mma<<<dim3(M_X / 128, N_W / 128), 256, SMEM_TOTAL>>>(bias);

    scan_seg_kernel<<<(NSEG * 16384) / 256, 256>>>();
    scan_prefix_kernel<<<16384 / 256, 256>>>(c0);
    scan_out_kernel<<<(NSEG * 16384) / 256, 256>>>(x, out);
}

// round 11
// speedup vs baseline: 7.3972x; 1.0117x over previous
#include <cuda_runtime.h>
#include <cuda_fp16.h>
#include <cstdint>
#include <math.h>

// ---------------------------------------------------------------------------
// Problem constants
// ---------------------------------------------------------------------------
#define L_SEQ 1024
#define B_SZ  16
#define D_SZ  1024
#define M_X   (L_SEQ * B_SZ)        // 16384 x-rows
#define N_W   3072                  // weight rows (gate-major permuted)
#define NPOS  16                    // physical k-positions (chunks of 64)
#define PLANE ((size_t)M_X * D_SZ)  // 16,777,216

#define NSEG 16
#define SEG_T (L_SEQ / NSEG)        // 64
#define NLANE (B_SZ * D_SZ)         // 16384

// ---------------------------------------------------------------------------
// Scratch (__device__ globals: allocation-free)
// ---------------------------------------------------------------------------
// Packed, pre-swizzled fp16 operands: [chunk][row][128B swizzled].
__device__ __align__(1024) __half g_xc[(size_t)M_X * 1024];   // 32 MiB
__device__ __align__(1024) __half g_wc[(size_t)N_W * 1024];   // 6 MiB
// GEMM outputs: u0, g1, g2 all fp16 planes
__device__ __half g_u0[PLANE];                                 // 33.5 MB
__device__ __half g_g1[PLANE];                                 // 33.5 MB
__device__ __half g_g2[PLANE];                                 // 33.5 MB
// Segmented-scan scratch
__device__ float g_segAx[NSEG * NLANE];
__device__ float g_segBx[NSEG * NLANE];
__device__ float g_cst  [NSEG * NLANE];

// ---------------------------------------------------------------------------
// helpers
// ---------------------------------------------------------------------------
__device__ __forceinline__ uint32_t smem_u32(const void* p) {
    return (uint32_t)__cvta_generic_to_shared(p);
}
__device__ __forceinline__ void cp_async16(uint32_t dst, const void* src) {
    asm volatile("cp.async.cg.shared.global [%0], [%1], 16;" :: "r"(dst), "l"(src));
}
__device__ __forceinline__ void cp_commit() {
    asm volatile("cp.async.commit_group;");
}
template <int N>
__device__ __forceinline__ void cp_wait() {
    asm volatile("cp.async.wait_group %0;" :: "n"(N));
}
__device__ __forceinline__ void ldsm_x4(uint32_t& r0, uint32_t& r1, uint32_t& r2,
                                        uint32_t& r3, uint32_t addr) {
    asm volatile("ldmatrix.sync.aligned.m8n8.x4.shared.b16 {%0,%1,%2,%3}, [%4];"
                 : "=r"(r0), "=r"(r1), "=r"(r2), "=r"(r3) : "r"(addr));
}
__device__ __forceinline__ void mma_fp16(float* d, const uint32_t* a, const uint32_t* b) {
    asm volatile(
        "mma.sync.aligned.m16n8k16.row.col.f32.f16.f16.f32 "
        "{%0,%1,%2,%3}, {%4,%5,%6,%7}, {%8,%9}, {%0,%1,%2,%3};"
        : "+f"(d[0]), "+f"(d[1]), "+f"(d[2]), "+f"(d[3])
        : "r"(a[0]), "r"(a[1]), "r"(a[2]), "r"(a[3]), "r"(b[0]), "r"(b[1]));
}
__device__ __forceinline__ uint32_t pack_h2(float a, float b) {
    __half2 h = __floats2half2_rn(a, b);
    return *reinterpret_cast<uint32_t*>(&h);
}

// ---------------------------------------------------------------------------
// Fused conversion kernel.
// Blocks [0, 8192): conv_x — X[m][k] fp32 -> packed swizzled fp16 tiles
// Blocks [8192, 14336): conv_w — W[k][3d+gate] -> rows n' = gate*1024+d
// ---------------------------------------------------------------------------
#define CONVX_BLOCKS 8192
#define CONVW_BLOCKS 6144

__global__ __launch_bounds__(256)
void conv_kernel(const float* __restrict__ X, const float* __restrict__ W) {
    if (blockIdx.x < CONVX_BLOCKS) {
        int gid = blockIdx.x * 256 + threadIdx.x;   // M_X * 128 threads
        int m  = gid >> 7;
        int k  = (gid & 127) * 8;

        const float4* xp = reinterpret_cast<const float4*>(X + (size_t)m * 1024 + k);
        float4 x0 = xp[0];
        float4 x1 = xp[1];

        uint4 hv;
        hv.x = pack_h2(x0.x, x0.y); hv.y = pack_h2(x0.z, x0.w);
        hv.z = pack_h2(x1.x, x1.y); hv.w = pack_h2(x1.z, x1.w);

        int chunk = k >> 6;
        uint32_t b = (uint32_t)(k & 63) * 2;
        uint32_t sw = b ^ (((uint32_t)m & 7u) << 4);
        char* base = (char*)g_xc;
        *reinterpret_cast<uint4*>(base + ((size_t)chunk * M_X + m) * 128 + sw) = hv;
    } else {
        int gid = (blockIdx.x - CONVX_BLOCKS) * 256 + threadIdx.x;  // N_W * 512
        int np = gid % N_W;
        int k  = (gid / N_W) * 2;

        int gate = np >> 10;
        int d    = np & 1023;
        int col  = 3 * d + gate;

        float w0 = W[(size_t)k * N_W + col];
        float w1 = W[(size_t)(k + 1) * N_W + col];

        int chunk = k >> 6;
        uint32_t b = (uint32_t)(k & 63) * 2;
        uint32_t sw = b ^ (((uint32_t)np & 7u) << 4);
        char* base = (char*)g_wc;
        *reinterpret_cast<uint32_t*>(base + ((size_t)chunk * N_W + np) * 128 + sw) =
            pack_h2(w0, w1);
    }
}

// ---------------------------------------------------------------------------
// mma.sync GEMM: C[np][m] = sum_k W[np][k] * X[m][k]  (fp16 single pass)
// CTA tile 128(np) x 128(m) x 64(k); 256 threads = 8 warps (2 np x 4 m).
// 3-stage x 32KB cp.async pipeline; 96KB smem => 2 CTAs/SM.
// ---------------------------------------------------------------------------
#define W_OFF 0
#define X_OFF 16384
#define STAGE_BYTES 32768        // W 16KB + X 16KB
#define STAGES 3
#define SMEM_TOTAL (STAGES * STAGE_BYTES)   // 98304 (96 KB)
#define EPI_PITCH 132            // floats per staging row (128 + pad)

__global__ __launch_bounds__(256, 2)
void sru_gemm_mma(const float* __restrict__ bias) {
    extern __shared__ char smem[];
    const uint32_t sbase = smem_u32(smem);
    const int tid = threadIdx.x;
    const int wid = tid >> 5;
    const int l = tid & 31;

    const int bn = blockIdx.x;    // m tiles (128)
    const int bm = blockIdx.y;    // np tiles (24)

    const int npwarp = (wid & 1) * 64;
    const int mwarp  = (wid >> 1) * 32;

    // ldmatrix per-lane addressing constants
    const uint32_t swz = (uint32_t)(l & 7) << 4;
    const uint32_t aRow = npwarp + (l & 15);
    const uint32_t aHalf = (uint32_t)(l >> 4) << 4;     // 0 or 16
    const uint32_t bRow = mwarp + (l & 7) + ((l & 16) >> 1);
    const uint32_t bHalf = (uint32_t)(l & 8) << 1;      // 0 or 16

    // cp.async sources for this CTA
    const char* aSrcBase = (const char*)g_wc + (size_t)bm * 128 * 128;
    const char* bSrcBase = (const char*)g_xc + (size_t)bn * 128 * 128;

    float cacc[4][4][4];
    #pragma unroll
    for (int i = 0; i < 4; i++)
        #pragma unroll
        for (int j = 0; j < 4; j++)
            #pragma unroll
            for (int r = 0; r < 4; r++) cacc[i][j][r] = 0.0f;

    // Load one k-position: W (16KB) + X (16KB)
    auto issue_pos = [&](int kc, int slot) {
        const uint32_t sb = sbase + slot * STAGE_BYTES;
        const char* wh = aSrcBase + (size_t)kc * N_W * 128;
        const char* xh = bSrcBase + (size_t)kc * M_X * 128;
        #pragma unroll
        for (int r = 0; r < 4; r++) {
            int off = (tid + r * 256) * 16;
            cp_async16(sb + W_OFF + off, wh + off);
        }
        #pragma unroll
        for (int r = 0; r < 4; r++) {
            int off = (tid + r * 256) * 16;
            cp_async16(sb + X_OFF + off, xh + off);
        }
        cp_commit();
    };

    issue_pos(0, 0);
    issue_pos(1, 1);

    for (int j = 0; j < NPOS; j++) {
        const int slot = j % 3;
        cp_wait<1>();
        __syncthreads();
        // Slot (j+2)%3 == (j-1)%3 was last read during compute of j-1; the
        // barrier above proves every warp finished that compute.
        if (j + 2 < NPOS) issue_pos(j + 2, (j + 2) % 3);

        const uint32_t sb = sbase + slot * STAGE_BYTES;

        #pragma unroll
        for (int ks = 0; ks < 4; ks++) {
            const uint32_t kb = ks * 32;
            const uint32_t aCol = (kb + aHalf) ^ swz;
            const uint32_t bCol = (kb + bHalf) ^ swz;

            uint32_t bh[2][4];
            #pragma unroll
            for (int g = 0; g < 2; g++) {
                ldsm_x4(bh[g][0], bh[g][1], bh[g][2], bh[g][3],
                        sb + X_OFF + (bRow + g * 16) * 128 + bCol);
            }
            #pragma unroll
            for (int t = 0; t < 4; t++) {
                uint32_t a[4];
                ldsm_x4(a[0], a[1], a[2], a[3],
                        sb + W_OFF + (aRow + t * 16) * 128 + aCol);
                #pragma unroll
                for (int jj = 0; jj < 4; jj++)
                    mma_fp16(cacc[t][jj], a, &bh[jj >> 1][(jj & 1) * 2]);
            }
        }
    }

    // ---------------- epilogue ----------------
    __syncthreads();   // done reading pipeline smem
    float* stag = (float*)smem;    // [128 m][EPI_PITCH np]  (67.6 KB < 96 KB)

    #pragma unroll
    for (int i = 0; i < 4; i++) {
        const int np0 = npwarp + i * 16 + (l >> 2);
        #pragma unroll
        for (int jj = 0; jj < 4; jj++) {
            const int m0 = mwarp + jj * 8 + (l & 3) * 2;
            stag[(size_t)m0 * EPI_PITCH + np0]           = cacc[i][jj][0];
            stag[(size_t)(m0 + 1) * EPI_PITCH + np0]     = cacc[i][jj][1];
            stag[(size_t)m0 * EPI_PITCH + np0 + 8]       = cacc[i][jj][2];
            stag[(size_t)(m0 + 1) * EPI_PITCH + np0 + 8] = cacc[i][jj][3];
        }
    }
    __syncthreads();

    // This CTA covers a single gate: np range [bm*128, bm*128+128)
    const int gate = bm >> 3;
    const int d0 = (bm & 7) * 128;
    __half* plane = (gate == 0) ? g_u0 : ((gate == 1) ? g_g1 : g_g2);

    // 128 m x 64 half2 stores
    for (int idx = tid; idx < 128 * 64; idx += 256) {
        const int m = idx >> 6;
        const int np2 = (idx & 63) * 2;
        float v0 = stag[(size_t)m * EPI_PITCH + np2];
        float v1 = stag[(size_t)m * EPI_PITCH + np2 + 1];
        if (gate) {
            const float b0 = bias[(gate - 1) * D_SZ + d0 + np2];
            const float b1 = bias[(gate - 1) * D_SZ + d0 + np2 + 1];
            v0 = 1.0f / (1.0f + __expf(-(v0 + b0)));
            v1 = 1.0f / (1.0f + __expf(-(v1 + b1)));
        }
        __half2 hv = __floats2half2_rn(v0, v1);
        *reinterpret_cast<__half2*>(
            &plane[(size_t)(bn * 128 + m) * D_SZ + d0 + np2]) = hv;
    }
}

// ---------------------------------------------------------------------------
// Segmented scan (vectorized: 2 lanes per thread).
// c_t = g1*c + u0*(1-g1)  (affine in c)
// ---------------------------------------------------------------------------
__global__ __launch_bounds__(256)
void scan_seg_kernel() {
    const int gid = blockIdx.x * blockDim.x + threadIdx.x;  // NSEG * 8192
    const int lane2 = (gid & 8191) * 2;
    const int s = gid >> 13;
    size_t o = ((size_t)s * SEG_T * NLANE + lane2) >> 1;    // half2 index
    const __half2* __restrict__ u0 = (const __half2*)g_u0;
    const __half2* __restrict__ g1 = (const __half2*)g_g1;
    float A0 = 1.0f, B0 = 0.0f, A1 = 1.0f, B1 = 0.0f;
    #pragma unroll 8
    for (int t = 0; t < SEG_T; t++) {
        const float2 a = __half22float2(g1[o]);
        const float2 u = __half22float2(u0[o]);
        B0 = B0 * a.x + u.x * (1.0f - a.x);
        B1 = B1 * a.y + u.y * (1.0f - a.y);
        A0 *= a.x;
        A1 *= a.y;
        o += NLANE / 2;
    }
    *reinterpret_cast<float2*>(&g_segAx[s * NLANE + lane2]) = make_float2(A0, A1);
    *reinterpret_cast<float2*>(&g_segBx[s * NLANE + lane2]) = make_float2(B0, B1);
}

__global__ __launch_bounds__(256)
void scan_prefix_kernel(const float* __restrict__ c0) {
    const int lane2 = (blockIdx.x * blockDim.x + threadIdx.x) * 2;  // 8192 threads
    float2 c = *reinterpret_cast<const float2*>(&c0[lane2]);
    #pragma unroll
    for (int s = 0; s < NSEG; s++) {
        *reinterpret_cast<float2*>(&g_cst[s * NLANE + lane2]) = c;
        const float2 A = *reinterpret_cast<const float2*>(&g_segAx[s * NLANE + lane2]);
        const float2 Bv = *reinterpret_cast<const float2*>(&g_segBx[s * NLANE + lane2]);
        c.x = A.x * c.x + Bv.x;
        c.y = A.y * c.y + Bv.y;
    }
}

__global__ __launch_bounds__(256)
void scan_out_kernel(const float* __restrict__ x, float* __restrict__ out) {
    const int gid = blockIdx.x * blockDim.x + threadIdx.x;  // NSEG * 8192
    const int lane2 = (gid & 8191) * 2;
    const int s = gid >> 13;
    const __half2* __restrict__ u0 = (const __half2*)g_u0;
    const __half2* __restrict__ g1 = (const __half2*)g_g1;
    const __half2* __restrict__ g2 = (const __half2*)g_g2;
    float2 c = *reinterpret_cast<const float2*>(&g_cst[s * NLANE + lane2]);
    size_t e = (size_t)s * SEG_T * NLANE + lane2;           // element index
    size_t o = e >> 1;                                      // half2 index
    #pragma unroll 4
    for (int t = 0; t < SEG_T; t++) {
        const float2 u = __half22float2(u0[o]);
        const float2 a = __half22float2(g1[o]);
        const float2 b = __half22float2(g2[o]);
        const float2 xv = *reinterpret_cast<const float2*>(&x[e]);
        c.x = (c.x - u.x) * a.x + u.x;
        c.y = (c.y - u.y) * a.y + u.y;
        float2 h;
        h.x = (tanhf(c.x) - xv.x) * b.x + xv.x;
        h.y = (tanhf(c.y) - xv.y) * b.y + xv.y;
        *reinterpret_cast<float2*>(&out[e]) = h;
        e += NLANE;
        o += NLANE / 2;
    }
    if (s == NSEG - 1)
        *reinterpret_cast<float2*>(&out[PLANE + lane2]) = c;   // c_last
}

// ---------------------------------------------------------------------------
// Launch
// ---------------------------------------------------------------------------
extern "C" void kernel_launch(void* const* d_in, const int* in_sizes, int n_in,
                              void* d_out, int out_size) {
    const float* x      = (const float*)d_in[0];  // (L,B,D)
    const float* weight = (const float*)d_in[1];  // (D, 3D)
    const float* bias   = (const float*)d_in[2];  // (2D)
    const float* c0     = (const float*)d_in[3];  // (B,D)
    float* out = (float*)d_out;                   // h then c_last

    conv_kernel<<<CONVX_BLOCKS + CONVW_BLOCKS, 256>>>(x, weight);

    static int smem_set = 0;
    if (!smem_set) {
        cudaFuncSetAttribute(sru_gemm_mma, cudaFuncAttributeMaxDynamicSharedMemorySize,
                             SMEM_TOTAL);
        smem_set = 1;
    }
    sru_gemm_mma<<<dim3(M_X / 128, N_W / 128), 256, SMEM_TOTAL>>>(bias);

    scan_seg_kernel<<<(NSEG * 8192) / 256, 256>>>();
    scan_prefix_kernel<<<8192 / 256, 256>>>(c0);
    scan_out_kernel<<<(NSEG * 8192) / 256, 256>>>(x, out);
}

// round 12
// speedup vs baseline: 7.6243x; 1.0307x over previous
#include <cuda_runtime.h>
#include <cuda_fp16.h>
#include <cstdint>
#include <math.h>

// ---------------------------------------------------------------------------
// Problem constants
// ---------------------------------------------------------------------------
#define L_SEQ 1024
#define B_SZ  16
#define D_SZ  1024
#define M_X   (L_SEQ * B_SZ)        // 16384 x-rows
#define N_W   3072                  // weight rows (gate-major permuted)
#define NPOS  16                    // physical k-positions (chunks of 64)
#define PLANE ((size_t)M_X * D_SZ)  // 16,777,216

#define NSEG 16
#define SEG_T (L_SEQ / NSEG)        // 64
#define NLANE (B_SZ * D_SZ)         // 16384

// ---------------------------------------------------------------------------
// Scratch (__device__ globals: allocation-free)
// ---------------------------------------------------------------------------
// Packed, pre-swizzled fp16 operands: [chunk][row][128B swizzled].
__device__ __align__(1024) __half g_xc[(size_t)M_X * 1024];   // 32 MiB
__device__ __align__(1024) __half g_wc[(size_t)N_W * 1024];   // 6 MiB
// GEMM outputs: u0, g1, g2 all fp16 planes
__device__ __half g_u0[PLANE];                                 // 33.5 MB
__device__ __half g_g1[PLANE];                                 // 33.5 MB
__device__ __half g_g2[PLANE];                                 // 33.5 MB
// Segmented-scan scratch
__device__ float g_segAx[NSEG * NLANE];
__device__ float g_segBx[NSEG * NLANE];
__device__ float g_cst  [NSEG * NLANE];

// ---------------------------------------------------------------------------
// helpers
// ---------------------------------------------------------------------------
__device__ __forceinline__ uint32_t smem_u32(const void* p) {
    return (uint32_t)__cvta_generic_to_shared(p);
}
__device__ __forceinline__ void cp_async16(uint32_t dst, const void* src) {
    asm volatile("cp.async.cg.shared.global [%0], [%1], 16;" :: "r"(dst), "l"(src));
}
__device__ __forceinline__ void cp_commit() {
    asm volatile("cp.async.commit_group;");
}
template <int N>
__device__ __forceinline__ void cp_wait() {
    asm volatile("cp.async.wait_group %0;" :: "n"(N));
}
__device__ __forceinline__ void ldsm_x4(uint32_t& r0, uint32_t& r1, uint32_t& r2,
                                        uint32_t& r3, uint32_t addr) {
    asm volatile("ldmatrix.sync.aligned.m8n8.x4.shared.b16 {%0,%1,%2,%3}, [%4];"
                 : "=r"(r0), "=r"(r1), "=r"(r2), "=r"(r3) : "r"(addr));
}
__device__ __forceinline__ void mma_fp16(float* d, const uint32_t* a, const uint32_t* b) {
    asm volatile(
        "mma.sync.aligned.m16n8k16.row.col.f32.f16.f16.f32 "
        "{%0,%1,%2,%3}, {%4,%5,%6,%7}, {%8,%9}, {%0,%1,%2,%3};"
        : "+f"(d[0]), "+f"(d[1]), "+f"(d[2]), "+f"(d[3])
        : "r"(a[0]), "r"(a[1]), "r"(a[2]), "r"(a[3]), "r"(b[0]), "r"(b[1]));
}
__device__ __forceinline__ uint32_t pack_h2(float a, float b) {
    __half2 h = __floats2half2_rn(a, b);
    return *reinterpret_cast<uint32_t*>(&h);
}

// ---------------------------------------------------------------------------
// Fused conversion kernel.
// Blocks [0, 8192): conv_x — X[m][k] fp32 -> packed swizzled fp16 tiles
// Blocks [8192, 14336): conv_w — W[k][3d+gate] -> rows n' = gate*1024+d
// ---------------------------------------------------------------------------
#define CONVX_BLOCKS 8192
#define CONVW_BLOCKS 6144

__global__ __launch_bounds__(256)
void conv_kernel(const float* __restrict__ X, const float* __restrict__ W) {
    if (blockIdx.x < CONVX_BLOCKS) {
        int gid = blockIdx.x * 256 + threadIdx.x;   // M_X * 128 threads
        int m  = gid >> 7;
        int k  = (gid & 127) * 8;

        const float4* xp = reinterpret_cast<const float4*>(X + (size_t)m * 1024 + k);
        float4 x0 = xp[0];
        float4 x1 = xp[1];

        uint4 hv;
        hv.x = pack_h2(x0.x, x0.y); hv.y = pack_h2(x0.z, x0.w);
        hv.z = pack_h2(x1.x, x1.y); hv.w = pack_h2(x1.z, x1.w);

        int chunk = k >> 6;
        uint32_t b = (uint32_t)(k & 63) * 2;
        uint32_t sw = b ^ (((uint32_t)m & 7u) << 4);
        char* base = (char*)g_xc;
        *reinterpret_cast<uint4*>(base + ((size_t)chunk * M_X + m) * 128 + sw) = hv;
    } else {
        int gid = (blockIdx.x - CONVX_BLOCKS) * 256 + threadIdx.x;  // N_W * 512
        int np = gid % N_W;
        int k  = (gid / N_W) * 2;

        int gate = np >> 10;
        int d    = np & 1023;
        int col  = 3 * d + gate;

        float w0 = W[(size_t)k * N_W + col];
        float w1 = W[(size_t)(k + 1) * N_W + col];

        int chunk = k >> 6;
        uint32_t b = (uint32_t)(k & 63) * 2;
        uint32_t sw = b ^ (((uint32_t)np & 7u) << 4);
        char* base = (char*)g_wc;
        *reinterpret_cast<uint32_t*>(base + ((size_t)chunk * N_W + np) * 128 + sw) =
            pack_h2(w0, w1);
    }
}

// ---------------------------------------------------------------------------
// mma.sync GEMM: C[np][m] = sum_k W[np][k] * X[m][k]  (fp16 single pass)
// CTA tile 128(np) x 128(m) x 64(k); 256 threads = 8 warps (2 np x 4 m).
// 3-stage x 32KB cp.async pipeline; 96KB smem => 2 CTAs/SM.
// ---------------------------------------------------------------------------
#define W_OFF 0
#define X_OFF 16384
#define STAGE_BYTES 32768        // W 16KB + X 16KB
#define STAGES 3
#define SMEM_TOTAL (STAGES * STAGE_BYTES)   // 98304 (96 KB)
#define EPI_PITCH 132            // floats per staging row (128 + pad)

__global__ __launch_bounds__(256, 2)
void sru_gemm_mma(const float* __restrict__ bias) {
    extern __shared__ char smem[];
    const uint32_t sbase = smem_u32(smem);
    const int tid = threadIdx.x;
    const int wid = tid >> 5;
    const int l = tid & 31;

    const int bn = blockIdx.x;    // m tiles (128)
    const int bm = blockIdx.y;    // np tiles (24)

    const int npwarp = (wid & 1) * 64;
    const int mwarp  = (wid >> 1) * 32;

    // ldmatrix per-lane addressing constants
    const uint32_t swz = (uint32_t)(l & 7) << 4;
    const uint32_t aRow = npwarp + (l & 15);
    const uint32_t aHalf = (uint32_t)(l >> 4) << 4;     // 0 or 16
    const uint32_t bRow = mwarp + (l & 7) + ((l & 16) >> 1);
    const uint32_t bHalf = (uint32_t)(l & 8) << 1;      // 0 or 16

    // cp.async sources for this CTA
    const char* aSrcBase = (const char*)g_wc + (size_t)bm * 128 * 128;
    const char* bSrcBase = (const char*)g_xc + (size_t)bn * 128 * 128;

    float cacc[4][4][4];
    #pragma unroll
    for (int i = 0; i < 4; i++)
        #pragma unroll
        for (int j = 0; j < 4; j++)
            #pragma unroll
            for (int r = 0; r < 4; r++) cacc[i][j][r] = 0.0f;

    // Load one k-position: W (16KB) + X (16KB)
    auto issue_pos = [&](int kc, int slot) {
        const uint32_t sb = sbase + slot * STAGE_BYTES;
        const char* wh = aSrcBase + (size_t)kc * N_W * 128;
        const char* xh = bSrcBase + (size_t)kc * M_X * 128;
        #pragma unroll
        for (int r = 0; r < 4; r++) {
            int off = (tid + r * 256) * 16;
            cp_async16(sb + W_OFF + off, wh + off);
        }
        #pragma unroll
        for (int r = 0; r < 4; r++) {
            int off = (tid + r * 256) * 16;
            cp_async16(sb + X_OFF + off, xh + off);
        }
        cp_commit();
    };

    issue_pos(0, 0);
    issue_pos(1, 1);

    for (int j = 0; j < NPOS; j++) {
        const int slot = j % 3;
        cp_wait<1>();
        __syncthreads();
        // Slot (j+2)%3 == (j-1)%3 was last read during compute of j-1; the
        // barrier above proves every warp finished that compute.
        if (j + 2 < NPOS) issue_pos(j + 2, (j + 2) % 3);

        const uint32_t sb = sbase + slot * STAGE_BYTES;

        #pragma unroll
        for (int ks = 0; ks < 4; ks++) {
            const uint32_t kb = ks * 32;
            const uint32_t aCol = (kb + aHalf) ^ swz;
            const uint32_t bCol = (kb + bHalf) ^ swz;

            uint32_t bh[2][4];
            #pragma unroll
            for (int g = 0; g < 2; g++) {
                ldsm_x4(bh[g][0], bh[g][1], bh[g][2], bh[g][3],
                        sb + X_OFF + (bRow + g * 16) * 128 + bCol);
            }
            #pragma unroll
            for (int t = 0; t < 4; t++) {
                uint32_t a[4];
                ldsm_x4(a[0], a[1], a[2], a[3],
                        sb + W_OFF + (aRow + t * 16) * 128 + aCol);
                #pragma unroll
                for (int jj = 0; jj < 4; jj++)
                    mma_fp16(cacc[t][jj], a, &bh[jj >> 1][(jj & 1) * 2]);
            }
        }
    }

    // ---------------- epilogue ----------------
    __syncthreads();   // done reading pipeline smem
    float* stag = (float*)smem;    // [128 m][EPI_PITCH np]  (67.6 KB < 96 KB)

    #pragma unroll
    for (int i = 0; i < 4; i++) {
        const int np0 = npwarp + i * 16 + (l >> 2);
        #pragma unroll
        for (int jj = 0; jj < 4; jj++) {
            const int m0 = mwarp + jj * 8 + (l & 3) * 2;
            stag[(size_t)m0 * EPI_PITCH + np0]           = cacc[i][jj][0];
            stag[(size_t)(m0 + 1) * EPI_PITCH + np0]     = cacc[i][jj][1];
            stag[(size_t)m0 * EPI_PITCH + np0 + 8]       = cacc[i][jj][2];
            stag[(size_t)(m0 + 1) * EPI_PITCH + np0 + 8] = cacc[i][jj][3];
        }
    }
    __syncthreads();

    // This CTA covers a single gate: np range [bm*128, bm*128+128)
    const int gate = bm >> 3;
    const int d0 = (bm & 7) * 128;
    __half* plane = (gate == 0) ? g_u0 : ((gate == 1) ? g_g1 : g_g2);

    // 128 m x 64 half2 stores
    for (int idx = tid; idx < 128 * 64; idx += 256) {
        const int m = idx >> 6;
        const int np2 = (idx & 63) * 2;
        float v0 = stag[(size_t)m * EPI_PITCH + np2];
        float v1 = stag[(size_t)m * EPI_PITCH + np2 + 1];
        if (gate) {
            const float b0 = bias[(gate - 1) * D_SZ + d0 + np2];
            const float b1 = bias[(gate - 1) * D_SZ + d0 + np2 + 1];
            v0 = 1.0f / (1.0f + __expf(-(v0 + b0)));
            v1 = 1.0f / (1.0f + __expf(-(v1 + b1)));
        }
        __half2 hv = __floats2half2_rn(v0, v1);
        *reinterpret_cast<__half2*>(
            &plane[(size_t)(bn * 128 + m) * D_SZ + d0 + np2]) = hv;
    }
}

// ---------------------------------------------------------------------------
// Segmented scan (vectorized: 2 lanes per thread).
// c_t = g1*c + u0*(1-g1)  (affine in c)
// ---------------------------------------------------------------------------
__global__ __launch_bounds__(256)
void scan_seg_kernel() {
    const int gid = blockIdx.x * blockDim.x + threadIdx.x;  // NSEG * 8192
    const int lane2 = (gid & 8191) * 2;
    const int s = gid >> 13;
    size_t o = ((size_t)s * SEG_T * NLANE + lane2) >> 1;    // half2 index
    const __half2* __restrict__ u0 = (const __half2*)g_u0;
    const __half2* __restrict__ g1 = (const __half2*)g_g1;
    float A0 = 1.0f, B0 = 0.0f, A1 = 1.0f, B1 = 0.0f;
    #pragma unroll 8
    for (int t = 0; t < SEG_T; t++) {
        const float2 a = __half22float2(g1[o]);
        const float2 u = __half22float2(u0[o]);
        B0 = B0 * a.x + u.x * (1.0f - a.x);
        B1 = B1 * a.y + u.y * (1.0f - a.y);
        A0 *= a.x;
        A1 *= a.y;
        o += NLANE / 2;
    }
    *reinterpret_cast<float2*>(&g_segAx[s * NLANE + lane2]) = make_float2(A0, A1);
    *reinterpret_cast<float2*>(&g_segBx[s * NLANE + lane2]) = make_float2(B0, B1);
}

// Prefix across segments: prefetch ALL segment coefficients first (MLP=32),
// then run the short dependent chain. One lane per thread.
__global__ __launch_bounds__(256)
void scan_prefix_kernel(const float* __restrict__ c0) {
    const int lane = blockIdx.x * blockDim.x + threadIdx.x;  // 16384 threads
    float A[NSEG], Bv[NSEG];
    #pragma unroll
    for (int s = 0; s < NSEG; s++) A[s] = g_segAx[s * NLANE + lane];
    #pragma unroll
    for (int s = 0; s < NSEG; s++) Bv[s] = g_segBx[s * NLANE + lane];
    float c = c0[lane];
    #pragma unroll
    for (int s = 0; s < NSEG; s++) {
        g_cst[s * NLANE + lane] = c;
        c = A[s] * c + Bv[s];
    }
}

__global__ __launch_bounds__(256)
void scan_out_kernel(float* __restrict__ out) {
    const int gid = blockIdx.x * blockDim.x + threadIdx.x;  // NSEG * 8192
    const int lane2 = (gid & 8191) * 2;
    const int s = gid >> 13;
    const __half2* __restrict__ u0 = (const __half2*)g_u0;
    const __half2* __restrict__ g1 = (const __half2*)g_g1;
    const __half2* __restrict__ g2 = (const __half2*)g_g2;
    float2 c = *reinterpret_cast<const float2*>(&g_cst[s * NLANE + lane2]);
    size_t e = (size_t)s * SEG_T * NLANE + lane2;           // element index
    size_t o = e >> 1;                                      // half2 index

    // x read from the packed swizzled fp16 operand g_xc.
    // element (m, d): chunk = d>>6, byte = (chunk*M_X + m)*128
    //                 + ((d&63)*2 ^ ((m&7)<<4));  here d fixed, m += 16 per t.
    const int m0 = (int)(e >> 10);          // initial row
    const int d  = lane2 & 1023;
    const char* xbase = (const char*)g_xc
        + ((size_t)(d >> 6) * M_X + m0) * 128
        + (((uint32_t)(d & 63) * 2) ^ (((uint32_t)m0 & 7u) << 4));

    #pragma unroll 4
    for (int t = 0; t < SEG_T; t++) {
        const float2 u = __half22float2(u0[o]);
        const float2 a = __half22float2(g1[o]);
        const float2 b = __half22float2(g2[o]);
        const float2 xv = __half22float2(
            *reinterpret_cast<const __half2*>(xbase + (size_t)t * 2048));
        c.x = (c.x - u.x) * a.x + u.x;
        c.y = (c.y - u.y) * a.y + u.y;
        float2 h;
        h.x = (tanhf(c.x) - xv.x) * b.x + xv.x;
        h.y = (tanhf(c.y) - xv.y) * b.y + xv.y;
        *reinterpret_cast<float2*>(&out[e]) = h;
        e += NLANE;
        o += NLANE / 2;
    }
    if (s == NSEG - 1)
        *reinterpret_cast<float2*>(&out[PLANE + lane2]) = c;   // c_last
}

// ---------------------------------------------------------------------------
// Launch
// ---------------------------------------------------------------------------
extern "C" void kernel_launch(void* const* d_in, const int* in_sizes, int n_in,
                              void* d_out, int out_size) {
    const float* x      = (const float*)d_in[0];  // (L,B,D)
    const float* weight = (const float*)d_in[1];  // (D, 3D)
    const float* bias   = (const float*)d_in[2];  // (2D)
    const float* c0     = (const float*)d_in[3];  // (B,D)
    float* out = (float*)d_out;                   // h then c_last

    conv_kernel<<<CONVX_BLOCKS + CONVW_BLOCKS, 256>>>(x, weight);

    static int smem_set = 0;
    if (!smem_set) {
        cudaFuncSetAttribute(sru_gemm_mma, cudaFuncAttributeMaxDynamicSharedMemorySize,
                             SMEM_TOTAL);
        smem_set = 1;
    }
    sru_gemm_mma<<<dim3(M_X / 128, N_W / 128), 256, SMEM_TOTAL>>>(bias);

    scan_seg_kernel<<<(NSEG * 8192) / 256, 256>>>();
    scan_prefix_kernel<<<NLANE / 256, 256>>>(c0);
    scan_out_kernel<<<(NSEG * 8192) / 256, 256>>>(out);
}